// round 10
// baseline (speedup 1.0000x reference)
#include <cuda_runtime.h>
#include <cuda_bf16.h>
#include <math.h>
#include <stdint.h>

#define T_Q 2048
#define T_K 2048
#define BATCH 4
#define EMB 1024
#define NHEADS 16
#define HDIM 64
#define MROWS (T_Q * BATCH)   // 8192
#define NEGINF -1e9f
#define NMASK (BATCH * T_K)   // 8192

// ---------------------------------------------------------------------------
// Static device scratch. All bf16 hi/lo pairs.
// ---------------------------------------------------------------------------
__device__ __nv_bfloat16 c_qh[MROWS * EMB], c_ql[MROWS * EMB];
__device__ __nv_bfloat16 c_kh[MROWS * EMB], c_kl[MROWS * EMB];
__device__ __nv_bfloat16 c_vh[MROWS * EMB], c_vl[MROWS * EMB];
__device__ __nv_bfloat16 c_wqh[EMB * EMB], c_wql[EMB * EMB];
__device__ __nv_bfloat16 c_wkh[EMB * EMB], c_wkl[EMB * EMB];
__device__ __nv_bfloat16 c_wvh[EMB * EMB], c_wvl[EMB * EMB];
__device__ __nv_bfloat16 c_woh[EMB * EMB], c_wol[EMB * EMB];
__device__ __nv_bfloat16 p_qh[MROWS * EMB], p_ql[MROWS * EMB];
__device__ __nv_bfloat16 p_kh[MROWS * EMB], p_kl[MROWS * EMB];
__device__ __nv_bfloat16 p_vh[MROWS * EMB], p_vl[MROWS * EMB];
__device__ __nv_bfloat16 ao_h[MROWS * EMB], ao_l[MROWS * EMB];
__device__ __align__(16) unsigned char g_mask[NMASK];
__device__ int g_mask_kind;

// ===========================================================================
// helpers
// ===========================================================================
__device__ __forceinline__ uint32_t smem_u32(const void* p) {
    uint32_t a;
    asm("{ .reg .u64 t; cvta.to.shared.u64 t, %1; cvt.u32.u64 %0, t; }"
        : "=r"(a) : "l"(p));
    return a;
}
__device__ __forceinline__ void mma16816(float* c, const uint32_t* a,
                                         uint32_t b0, uint32_t b1) {
    asm volatile(
        "mma.sync.aligned.m16n8k16.row.col.f32.bf16.bf16.f32 "
        "{%0,%1,%2,%3}, {%4,%5,%6,%7}, {%8,%9}, {%0,%1,%2,%3};"
        : "+f"(c[0]), "+f"(c[1]), "+f"(c[2]), "+f"(c[3])
        : "r"(a[0]), "r"(a[1]), "r"(a[2]), "r"(a[3]), "r"(b0), "r"(b1));
}
__device__ __forceinline__ void ldsm_x4(uint32_t* r, uint32_t addr) {
    asm volatile("ldmatrix.sync.aligned.m8n8.x4.shared.b16 {%0,%1,%2,%3}, [%4];"
        : "=r"(r[0]), "=r"(r[1]), "=r"(r[2]), "=r"(r[3]) : "r"(addr));
}
__device__ __forceinline__ void ldsm_x4_t(uint32_t* r, uint32_t addr) {
    asm volatile("ldmatrix.sync.aligned.m8n8.x4.trans.shared.b16 {%0,%1,%2,%3}, [%4];"
        : "=r"(r[0]), "=r"(r[1]), "=r"(r[2]), "=r"(r[3]) : "r"(addr));
}
__device__ __forceinline__ void cp16(uint32_t sm, const void* g) {
    asm volatile("cp.async.cg.shared.global [%0], [%1], 16;" :: "r"(sm), "l"(g));
}
#define CP_COMMIT() asm volatile("cp.async.commit_group;" ::: "memory")
#define CP_WAIT(n)  asm volatile("cp.async.wait_group %0;" :: "n"(n) : "memory")

__device__ __forceinline__ void split1(float x, __nv_bfloat16& h, __nv_bfloat16& l) {
    h = __float2bfloat16(x);
    l = __float2bfloat16(x - __bfloat162float(h));
}
__device__ __forceinline__ uint32_t pack2(__nv_bfloat16 a, __nv_bfloat16 b) {
    return (uint32_t)__bfloat16_as_ushort(a) | ((uint32_t)__bfloat16_as_ushort(b) << 16);
}
__device__ __forceinline__ void split4(float4 v, uint2& hw, uint2& lw) {
    __nv_bfloat16 h0, h1, h2, h3, l0, l1, l2, l3;
    split1(v.x, h0, l0); split1(v.y, h1, l1);
    split1(v.z, h2, l2); split1(v.w, h3, l3);
    hw.x = pack2(h0, h1); hw.y = pack2(h2, h3);
    lw.x = pack2(l0, l1); lw.y = pack2(l2, l3);
}

// ===========================================================================
// batched fp32 -> bf16 hi/lo converters
// ===========================================================================
__global__ void conv_qkv(const float* __restrict__ q, const float* __restrict__ k,
                         const float* __restrict__ v,
                         __nv_bfloat16* __restrict__ qh, __nv_bfloat16* __restrict__ ql,
                         __nv_bfloat16* __restrict__ kh, __nv_bfloat16* __restrict__ kl,
                         __nv_bfloat16* __restrict__ vh, __nv_bfloat16* __restrict__ vl)
{
    const float* x = (blockIdx.y == 0) ? q : (blockIdx.y == 1) ? k : v;
    __nv_bfloat16* h = (blockIdx.y == 0) ? qh : (blockIdx.y == 1) ? kh : vh;
    __nv_bfloat16* l = (blockIdx.y == 0) ? ql : (blockIdx.y == 1) ? kl : vl;
    int i = (blockIdx.x * blockDim.x + threadIdx.x) * 4;
    float4 vv = *(const float4*)(x + i);
    uint2 hw, lw;
    split4(vv, hw, lw);
    *(uint2*)(h + i) = hw;
    *(uint2*)(l + i) = lw;
}

__global__ void conv_w(const float* __restrict__ w0, const float* __restrict__ w1,
                       const float* __restrict__ w2, const float* __restrict__ w3,
                       __nv_bfloat16* __restrict__ h0, __nv_bfloat16* __restrict__ l0,
                       __nv_bfloat16* __restrict__ h1, __nv_bfloat16* __restrict__ l1,
                       __nv_bfloat16* __restrict__ h2, __nv_bfloat16* __restrict__ l2,
                       __nv_bfloat16* __restrict__ h3, __nv_bfloat16* __restrict__ l3)
{
    int wsel = blockIdx.y;
    const float* x = (wsel == 0) ? w0 : (wsel == 1) ? w1 : (wsel == 2) ? w2 : w3;
    __nv_bfloat16* h = (wsel == 0) ? h0 : (wsel == 1) ? h1 : (wsel == 2) ? h2 : h3;
    __nv_bfloat16* l = (wsel == 0) ? l0 : (wsel == 1) ? l1 : (wsel == 2) ? l2 : l3;
    int i = (blockIdx.x * blockDim.x + threadIdx.x) * 4;
    float4 vv = *(const float4*)(x + i);
    uint2 hw, lw;
    split4(vv, hw, lw);
    *(uint2*)(h + i) = hw;
    *(uint2*)(l + i) = lw;
}

// ===========================================================================
// Mask dtype sniff + normalization (verified R3)
// ===========================================================================
__global__ void sniff_mask_kernel(const unsigned char* __restrict__ m)
{
    __shared__ int nz_off, nz_al;
    if (threadIdx.x == 0) { nz_off = 0; nz_al = 0; }
    __syncthreads();
    int loc_off = 0, loc_al = 0;
    for (int i = threadIdx.x; i < NMASK; i += blockDim.x) {
        unsigned char v = m[i];
        if (v) { if (i & 3) loc_off = 1; else loc_al = 1; }
    }
    if (loc_off) atomicOr(&nz_off, 1);
    if (loc_al)  atomicOr(&nz_al, 1);
    __syncthreads();
    if (threadIdx.x == 0) {
        int kind;
        if (!nz_off)     kind = 1;
        else if (!nz_al) kind = 2;
        else             kind = 0;
        g_mask_kind = kind;
    }
}

__global__ void norm_mask_kernel(const void* __restrict__ m)
{
    int i = blockIdx.x * blockDim.x + threadIdx.x;
    if (i >= NMASK) return;
    int kind = g_mask_kind;
    unsigned char r;
    if (kind == 1)      r = (((const int*)m)[i]   != 0);
    else if (kind == 2) r = (((const float*)m)[i] != 0.f);
    else                r = (((const unsigned char*)m)[i] != 0);
    g_mask[i] = r;
}

// ===========================================================================
// HMMA GEMM NT core: C = A*B^T, bf16 hi/lo x3 chains, R7 pipeline
// (issue -> commit -> wait(1) -> sync -> compute -> sync). CTA 128x128, BK=32.
// ===========================================================================
#define GBM 128
#define GBN 128
#define GBK 32
#define GSTR 40
#define ARR_SZ (128 * GSTR * 2)
#define STAGE_SZ (4 * ARR_SZ)
#define GEMM_SMEM (2 * STAGE_SZ)
#define O_AH 0
#define O_AL ARR_SZ
#define O_BH (2 * ARR_SZ)
#define O_BL (3 * ARR_SZ)

extern __shared__ char sm_raw[];

template <int OUTMODE>
__device__ __forceinline__ void gemm_core(
    const __nv_bfloat16* __restrict__ Agh, const __nv_bfloat16* __restrict__ Agl,
    const __nv_bfloat16* __restrict__ Bgh, const __nv_bfloat16* __restrict__ Bgl,
    float* __restrict__ Cf,
    __nv_bfloat16* __restrict__ Ch, __nv_bfloat16* __restrict__ Cl)
{
    uint32_t sb = smem_u32(sm_raw);
    const int tid = threadIdx.x;
    const int wid = tid >> 5;
    const int lane = tid & 31;
    const int wm = (wid & 1) * 64;
    const int wn = (wid >> 1) * 32;
    const size_t rowA0 = (size_t)blockIdx.y * GBM;
    const size_t rowB0 = (size_t)blockIdx.x * GBN;

    const int carr = tid >> 6;
    const int crow0 = (tid & 63) >> 1;
    const int cseg = (tid & 1) << 1;
    const __nv_bfloat16* gbase[4] = {
        Agh + rowA0 * EMB, Agl + rowA0 * EMB,
        Bgh + rowB0 * EMB, Bgl + rowB0 * EMB };
    const __nv_bfloat16* mygb = gbase[carr];
    const uint32_t myarr = sb + carr * ARR_SZ;

    float acc[4][4][4];
#pragma unroll
    for (int mt = 0; mt < 4; mt++)
#pragma unroll
        for (int nt = 0; nt < 4; nt++)
#pragma unroll
            for (int e = 0; e < 4; e++) acc[mt][nt][e] = 0.f;

    const int NCH = EMB / GBK;   // 32

    // prologue: prefetch chunk 0 -> stage 0
#pragma unroll
    for (int rr = 0; rr < 4; rr++) {
        int row = crow0 + rr * 32;
        uint32_t smaddr = myarr + row * (GSTR * 2) + cseg * 16;
        const void* g = mygb + (size_t)row * EMB + cseg * 8;
        cp16(smaddr, g);
        cp16(smaddr + 16, (const char*)g + 16);
    }
    CP_COMMIT();

    for (int c = 0; c < NCH; c++) {
        if (c + 1 < NCH) {
            const int kt = (c + 1) * GBK;
            const uint32_t stb = myarr + ((c + 1) & 1) * STAGE_SZ;
#pragma unroll
            for (int rr = 0; rr < 4; rr++) {
                int row = crow0 + rr * 32;
                uint32_t smaddr = stb + row * (GSTR * 2) + cseg * 16;
                const void* g = mygb + (size_t)row * EMB + kt + cseg * 8;
                cp16(smaddr, g);
                cp16(smaddr + 16, (const char*)g + 16);
            }
            CP_COMMIT();
            CP_WAIT(1);
        } else {
            CP_WAIT(0);
        }
        __syncthreads();

        const uint32_t base = sb + (uint32_t)(c & 1) * STAGE_SZ;
        const uint32_t lrow = lane & 15;
        const uint32_t lcol = (lane >> 4) << 3;
#pragma unroll
        for (int kk = 0; kk < GBK; kk += 16) {
            uint32_t af[4][4];
#pragma unroll
            for (int mt = 0; mt < 4; mt++) {
                uint32_t addr = base + O_AH +
                    (uint32_t)(((wm + mt * 16 + lrow) * GSTR + kk + lcol) * 2);
                ldsm_x4(af[mt], addr);
            }
            uint32_t b0h[4], b1h[4], b0l[4], b1l[4];
#pragma unroll
            for (int g = 0; g < 2; g++) {
                uint32_t roff = (uint32_t)(((wn + g * 16 + lrow) * GSTR + kk + lcol) * 2);
                uint32_t r4[4];
                ldsm_x4(r4, base + O_BH + roff);
                b0h[2 * g] = r4[0]; b0h[2 * g + 1] = r4[1];
                b1h[2 * g] = r4[2]; b1h[2 * g + 1] = r4[3];
                ldsm_x4(r4, base + O_BL + roff);
                b0l[2 * g] = r4[0]; b0l[2 * g + 1] = r4[1];
                b1l[2 * g] = r4[2]; b1l[2 * g + 1] = r4[3];
            }
#pragma unroll
            for (int mt = 0; mt < 4; mt++)
#pragma unroll
                for (int nt = 0; nt < 4; nt++) {
                    mma16816(acc[mt][nt], af[mt], b0h[nt], b1h[nt]);
                    mma16816(acc[mt][nt], af[mt], b0l[nt], b1l[nt]);
                }
#pragma unroll
            for (int mt = 0; mt < 4; mt++) {
                uint32_t addr = base + O_AL +
                    (uint32_t)(((wm + mt * 16 + lrow) * GSTR + kk + lcol) * 2);
                ldsm_x4(af[mt], addr);
            }
#pragma unroll
            for (int mt = 0; mt < 4; mt++)
#pragma unroll
                for (int nt = 0; nt < 4; nt++)
                    mma16816(acc[mt][nt], af[mt], b0h[nt], b1h[nt]);
        }
        __syncthreads();
    }

#pragma unroll
    for (int mt = 0; mt < 4; mt++) {
        size_t r0 = rowA0 + wm + mt * 16 + (lane >> 2);
        size_t r1 = r0 + 8;
#pragma unroll
        for (int nt = 0; nt < 4; nt++) {
            size_t cc = rowB0 + wn + nt * 8 + (lane & 3) * 2;
            if (OUTMODE == 0) {
                *(float2*)(Cf + r0 * EMB + cc) = make_float2(acc[mt][nt][0], acc[mt][nt][1]);
                *(float2*)(Cf + r1 * EMB + cc) = make_float2(acc[mt][nt][2], acc[mt][nt][3]);
            } else {
                __nv_bfloat16 h0, l0, h1, l1;
                split1(acc[mt][nt][0], h0, l0);
                split1(acc[mt][nt][1], h1, l1);
                *(uint32_t*)(Ch + r0 * EMB + cc) = pack2(h0, h1);
                *(uint32_t*)(Cl + r0 * EMB + cc) = pack2(l0, l1);
                split1(acc[mt][nt][2], h0, l0);
                split1(acc[mt][nt][3], h1, l1);
                *(uint32_t*)(Ch + r1 * EMB + cc) = pack2(h0, h1);
                *(uint32_t*)(Cl + r1 * EMB + cc) = pack2(l0, l1);
            }
        }
    }
}

// merged Q/K/V projection launch (blockIdx.z selects the problem)
__global__ __launch_bounds__(256, 2) void gemm_qkv(
    const __nv_bfloat16* qh, const __nv_bfloat16* ql,
    const __nv_bfloat16* kh, const __nv_bfloat16* kl,
    const __nv_bfloat16* vh, const __nv_bfloat16* vl,
    const __nv_bfloat16* wqh, const __nv_bfloat16* wql,
    const __nv_bfloat16* wkh, const __nv_bfloat16* wkl,
    const __nv_bfloat16* wvh, const __nv_bfloat16* wvl,
    __nv_bfloat16* pqh, __nv_bfloat16* pql,
    __nv_bfloat16* pkh, __nv_bfloat16* pkl,
    __nv_bfloat16* pvh, __nv_bfloat16* pvl)
{
    const int z = blockIdx.z;
    const __nv_bfloat16* Agh = (z == 0) ? qh : (z == 1) ? kh : vh;
    const __nv_bfloat16* Agl = (z == 0) ? ql : (z == 1) ? kl : vl;
    const __nv_bfloat16* Bgh = (z == 0) ? wqh : (z == 1) ? wkh : wvh;
    const __nv_bfloat16* Bgl = (z == 0) ? wql : (z == 1) ? wkl : wvl;
    __nv_bfloat16* Ch = (z == 0) ? pqh : (z == 1) ? pkh : pvh;
    __nv_bfloat16* Cl = (z == 0) ? pql : (z == 1) ? pkl : pvl;
    gemm_core<1>(Agh, Agl, Bgh, Bgl, nullptr, Ch, Cl);
}

__global__ __launch_bounds__(256, 2) void gemm_out(
    const __nv_bfloat16* Agh, const __nv_bfloat16* Agl,
    const __nv_bfloat16* Bgh, const __nv_bfloat16* Bgl,
    float* Cf)
{
    gemm_core<0>(Agh, Agl, Bgh, Bgl, Cf, nullptr, nullptr);
}

// ===========================================================================
// FA2 flash attention: 128 q/CTA, warp = 16q x 64k, register softmax,
// register-resident P, Q frags in registers, 3-STAGE cp.async K/V ring:
// one barrier per tile, >=1 load group always in flight.
// ===========================================================================
#define AQ 128
#define AK 64
#define ASTR 72
#define AROWB (ASTR * 2)       // 144 B per smem row
#define KVROWS (AK * AROWB)    // 9216 B per K/V array per stage
#define NSTG 3

struct AttnSmem {
    __nv_bfloat16 Qh[AQ][ASTR], Ql[AQ][ASTR];            // 36,864
    __nv_bfloat16 Kh[NSTG][AK][ASTR], Kl[NSTG][AK][ASTR];// 55,296
    __nv_bfloat16 Vh[NSTG][AK][ASTR], Vl[NSTG][AK][ASTR];// 55,296
    unsigned char msk[NSTG][64];                         // 192
};
#define ATTN_SMEM ((int)sizeof(AttnSmem))

__global__ __launch_bounds__(256) void attn_mma(
    const __nv_bfloat16* __restrict__ Qhg, const __nv_bfloat16* __restrict__ Qlg,
    const __nv_bfloat16* __restrict__ Khg, const __nv_bfloat16* __restrict__ Klg,
    const __nv_bfloat16* __restrict__ Vhg, const __nv_bfloat16* __restrict__ Vlg,
    const unsigned char* __restrict__ mask,
    __nv_bfloat16* __restrict__ Ohg, __nv_bfloat16* __restrict__ Olg)
{
    AttnSmem& s = *reinterpret_cast<AttnSmem*>(sm_raw);
    const int b  = blockIdx.z;
    const int h  = blockIdx.y;
    const int qt = blockIdx.x;
    const int tid = threadIdx.x;
    const int wid = tid >> 5;
    const int lane = tid & 31;
    const size_t headoff = (size_t)h * HDIM;

    const uint32_t sqh = smem_u32(&s.Qh[0][0]);
    const uint32_t sql = smem_u32(&s.Ql[0][0]);
    const uint32_t skh = smem_u32(&s.Kh[0][0][0]);
    const uint32_t skl = smem_u32(&s.Kl[0][0][0]);
    const uint32_t svh = smem_u32(&s.Vh[0][0][0]);
    const uint32_t svl = smem_u32(&s.Vl[0][0][0]);
    const uint32_t smk = smem_u32(&s.msk[0][0]);

    // --- cp.async assignment: tid>>6 -> array, tid&63 -> row ---
    const int ca = tid >> 6;
    const int crow = tid & 63;
    const __nv_bfloat16* casrc = (ca == 0) ? Khg : (ca == 1) ? Klg
                                : (ca == 2) ? Vhg : Vlg;
    const uint32_t cadst = (ca == 0) ? skh : (ca == 1) ? skl
                          : (ca == 2) ? svh : svl;

    const int NT = T_K / AK;     // 32

    // prologue: issue tiles 0 and 1 into stages 0, 1 (separate groups)
#pragma unroll
    for (int p = 0; p < 2; p++) {
        size_t gi = ((size_t)(p * AK + crow) * BATCH + b) * EMB + headoff;
        const char* g = (const char*)(casrc + gi);
        uint32_t d = cadst + p * KVROWS + crow * AROWB;
#pragma unroll
        for (int seg = 0; seg < 8; seg++) cp16(d + seg * 16, g + seg * 16);
        if (tid < 4) cp16(smk + p * 64 + tid * 16,
                          mask + (size_t)b * T_K + p * AK + tid * 16);
        CP_COMMIT();
    }

    // --- Q tile -> smem (regular stores, overlapped with cp.async) ---
#pragma unroll
    for (int t = 0; t < 4; t++) {
        int i = tid + t * 256;
        int r = i >> 3, seg = i & 7;
        size_t gi = ((size_t)(qt * AQ + r) * BATCH + b) * EMB + headoff + seg * 8;
        *(uint4*)((char*)&s.Qh[r][0] + seg * 16) = *(const uint4*)(Qhg + gi);
        *(uint4*)((char*)&s.Ql[r][0] + seg * 16) = *(const uint4*)(Qlg + gi);
    }
    __syncthreads();

    // --- hoist Q fragments to registers (loop-invariant) ---
    const uint32_t lrow = lane & 15;
    const uint32_t lcol = (lane >> 4) << 3;
    uint32_t qfh[4][4], qfl[4][4];
#pragma unroll
    for (int kk = 0; kk < 4; kk++) {
        uint32_t aoff = (uint32_t)(((wid * 16 + lrow) * ASTR + kk * 16 + lcol) * 2);
        ldsm_x4(qfh[kk], sqh + aoff);
        ldsm_x4(qfl[kk], sql + aoff);
    }

    float m0 = -INFINITY, m1 = -INFINITY, l0 = 0.f, l1 = 0.f;
    float o[8][4];
#pragma unroll
    for (int nt = 0; nt < 8; nt++)
#pragma unroll
        for (int e = 0; e < 4; e++) o[nt][e] = 0.f;

    for (int kt = 0; kt < NT; kt++) {
        // wait for tile kt (issued 2 iterations back -> usually resident)
        if (kt + 1 < NT) { CP_WAIT(1); } else { CP_WAIT(0); }
        __syncthreads();
        // issue tile kt+2 into stage (kt+2)%3 — its readers (iter kt-1)
        // finished at the barrier above
        if (kt + 2 < NT) {
            int st2 = (kt + 2) % NSTG;
            size_t gi = ((size_t)((kt + 2) * AK + crow) * BATCH + b) * EMB + headoff;
            const char* g = (const char*)(casrc + gi);
            uint32_t d = cadst + st2 * KVROWS + crow * AROWB;
#pragma unroll
            for (int seg = 0; seg < 8; seg++) cp16(d + seg * 16, g + seg * 16);
            if (tid < 4)
                cp16(smk + st2 * 64 + tid * 16,
                     mask + (size_t)b * T_K + (kt + 2) * AK + tid * 16);
            CP_COMMIT();
        }

        const int st = kt % NSTG;
        const uint32_t kbh = skh + st * KVROWS;
        const uint32_t kbl = skl + st * KVROWS;
        const uint32_t vbh = svh + st * KVROWS;
        const uint32_t vbl = svl + st * KVROWS;
        const unsigned char* mrow = &s.msk[st][0];

        // ---- S = Q K^T (warp: 16q x 64k), 3 chains ----
        float sc[8][4];
#pragma unroll
        for (int nt = 0; nt < 8; nt++)
#pragma unroll
            for (int e = 0; e < 4; e++) sc[nt][e] = 0.f;

#pragma unroll
        for (int kk = 0; kk < 4; kk++) {
            uint32_t b0h[8], b1h[8], b0l[8], b1l[8];
#pragma unroll
            for (int g = 0; g < 4; g++) {
                uint32_t roff = (uint32_t)(((g * 16 + lrow) * ASTR + kk * 16 + lcol) * 2);
                uint32_t r4[4];
                ldsm_x4(r4, kbh + roff);
                b0h[2*g] = r4[0]; b0h[2*g+1] = r4[1];
                b1h[2*g] = r4[2]; b1h[2*g+1] = r4[3];
                ldsm_x4(r4, kbl + roff);
                b0l[2*g] = r4[0]; b0l[2*g+1] = r4[1];
                b1l[2*g] = r4[2]; b1l[2*g+1] = r4[3];
            }
#pragma unroll
            for (int nt = 0; nt < 8; nt++) {
                mma16816(sc[nt], qfh[kk], b0h[nt], b1h[nt]);
                mma16816(sc[nt], qfh[kk], b0l[nt], b1l[nt]);
                mma16816(sc[nt], qfl[kk], b0h[nt], b1h[nt]);
            }
        }

        // ---- register softmax ----
        float tm0 = -INFINITY, tm1 = -INFINITY;
#pragma unroll
        for (int nt = 0; nt < 8; nt++) {
            int k0 = nt * 8 + (lane & 3) * 2;
            bool mk0 = mrow[k0] != 0, mk1 = mrow[k0 + 1] != 0;
            sc[nt][0] = mk0 ? NEGINF : sc[nt][0] * 0.125f;
            sc[nt][1] = mk1 ? NEGINF : sc[nt][1] * 0.125f;
            sc[nt][2] = mk0 ? NEGINF : sc[nt][2] * 0.125f;
            sc[nt][3] = mk1 ? NEGINF : sc[nt][3] * 0.125f;
            tm0 = fmaxf(tm0, fmaxf(sc[nt][0], sc[nt][1]));
            tm1 = fmaxf(tm1, fmaxf(sc[nt][2], sc[nt][3]));
        }
        tm0 = fmaxf(tm0, __shfl_xor_sync(0xffffffffu, tm0, 1));
        tm0 = fmaxf(tm0, __shfl_xor_sync(0xffffffffu, tm0, 2));
        tm1 = fmaxf(tm1, __shfl_xor_sync(0xffffffffu, tm1, 1));
        tm1 = fmaxf(tm1, __shfl_xor_sync(0xffffffffu, tm1, 2));

        float mn0 = fmaxf(m0, tm0), mn1 = fmaxf(m1, tm1);
        float al0 = __expf(m0 - mn0), al1 = __expf(m1 - mn1);
        m0 = mn0; m1 = mn1;

        float ts0 = 0.f, ts1 = 0.f;
        uint32_t pfh[4][4], pfl[4][4];
#pragma unroll
        for (int nt = 0; nt < 8; nt++) {
            float p0 = __expf(sc[nt][0] - mn0);
            float p1 = __expf(sc[nt][1] - mn0);
            float p2 = __expf(sc[nt][2] - mn1);
            float p3 = __expf(sc[nt][3] - mn1);
            ts0 += p0 + p1;
            ts1 += p2 + p3;
            __nv_bfloat16 h0, lo0, h1, lo1;
            int t = nt >> 1, half = (nt & 1) * 2;
            split1(p0, h0, lo0); split1(p1, h1, lo1);
            pfh[t][half + 0] = pack2(h0, h1);
            pfl[t][half + 0] = pack2(lo0, lo1);
            split1(p2, h0, lo0); split1(p3, h1, lo1);
            pfh[t][half + 1] = pack2(h0, h1);
            pfl[t][half + 1] = pack2(lo0, lo1);
        }
        ts0 += __shfl_xor_sync(0xffffffffu, ts0, 1);
        ts0 += __shfl_xor_sync(0xffffffffu, ts0, 2);
        ts1 += __shfl_xor_sync(0xffffffffu, ts1, 1);
        ts1 += __shfl_xor_sync(0xffffffffu, ts1, 2);
        l0 = l0 * al0 + ts0;
        l1 = l1 * al1 + ts1;

#pragma unroll
        for (int nt = 0; nt < 8; nt++) {
            o[nt][0] *= al0; o[nt][1] *= al0;
            o[nt][2] *= al1; o[nt][3] *= al1;
        }

        // ---- O += P V (warp: 16q x 64d), 3 chains ----
#pragma unroll
        for (int t = 0; t < 4; t++) {
            uint32_t b0h[8], b1h[8], b0l[8], b1l[8];
#pragma unroll
            for (int g = 0; g < 4; g++) {
                uint32_t vrow = (uint32_t)(t * 16 + (lane & 7) + ((lane >> 3) & 1) * 8);
                uint32_t vcol = (uint32_t)(g * 16 + ((lane >> 4) << 3));
                uint32_t roff = (vrow * ASTR + vcol) * 2;
                uint32_t r4[4];
                ldsm_x4_t(r4, vbh + roff);
                b0h[2*g] = r4[0]; b1h[2*g] = r4[1];
                b0h[2*g+1] = r4[2]; b1h[2*g+1] = r4[3];
                ldsm_x4_t(r4, vbl + roff);
                b0l[2*g] = r4[0]; b1l[2*g] = r4[1];
                b0l[2*g+1] = r4[2]; b1l[2*g+1] = r4[3];
            }
#pragma unroll
            for (int nt = 0; nt < 8; nt++) {
                mma16816(o[nt], pfh[t], b0h[nt], b1h[nt]);
                mma16816(o[nt], pfh[t], b0l[nt], b1l[nt]);
                mma16816(o[nt], pfl[t], b0h[nt], b1h[nt]);
            }
        }
    }

    // ---- finalize ----
    float inv0 = 1.f / l0;
    float inv1 = 1.f / l1;
    const int r0 = wid * 16 + (lane >> 2);
    const int r1 = r0 + 8;
    size_t tg0 = (size_t)(qt * AQ + r0) * BATCH + b;
    size_t tg1 = (size_t)(qt * AQ + r1) * BATCH + b;
#pragma unroll
    for (int nt = 0; nt < 8; nt++) {
        size_t d0 = nt * 8 + (lane & 3) * 2;
        __nv_bfloat16 h0, lo0, h1, lo1;
        split1(o[nt][0] * inv0, h0, lo0);
        split1(o[nt][1] * inv0, h1, lo1);
        *(uint32_t*)(Ohg + tg0 * EMB + headoff + d0) = pack2(h0, h1);
        *(uint32_t*)(Olg + tg0 * EMB + headoff + d0) = pack2(lo0, lo1);
        split1(o[nt][2] * inv1, h0, lo0);
        split1(o[nt][3] * inv1, h1, lo1);
        *(uint32_t*)(Ohg + tg1 * EMB + headoff + d0) = pack2(h0, h1);
        *(uint32_t*)(Olg + tg1 * EMB + headoff + d0) = pack2(lo0, lo1);
    }
}

// ===========================================================================
// Launch
// ===========================================================================
extern "C" void kernel_launch(void* const* d_in, const int* in_sizes, int n_in,
                              void* d_out, int out_size)
{
    const float* q  = (const float*)d_in[0];
    const float* k  = (const float*)d_in[1];
    const float* v  = (const float*)d_in[2];
    const void*  maskraw = d_in[3];
    const float* Wq = (const float*)d_in[4];
    const float* Wk = (const float*)d_in[5];
    const float* Wv = (const float*)d_in[6];
    const float* Wo = (const float*)d_in[7];
    float* out = (float*)d_out;

    __nv_bfloat16 *qh, *ql, *kh, *kl, *vh, *vl;
    __nv_bfloat16 *wqh, *wql, *wkh, *wkl, *wvh, *wvl, *woh, *wol;
    __nv_bfloat16 *pqh, *pql, *pkh, *pkl, *pvh, *pvl, *aoh, *aol;
    unsigned char* gmask;
    cudaGetSymbolAddress((void**)&qh, c_qh);  cudaGetSymbolAddress((void**)&ql, c_ql);
    cudaGetSymbolAddress((void**)&kh, c_kh);  cudaGetSymbolAddress((void**)&kl, c_kl);
    cudaGetSymbolAddress((void**)&vh, c_vh);  cudaGetSymbolAddress((void**)&vl, c_vl);
    cudaGetSymbolAddress((void**)&wqh, c_wqh); cudaGetSymbolAddress((void**)&wql, c_wql);
    cudaGetSymbolAddress((void**)&wkh, c_wkh); cudaGetSymbolAddress((void**)&wkl, c_wkl);
    cudaGetSymbolAddress((void**)&wvh, c_wvh); cudaGetSymbolAddress((void**)&wvl, c_wvl);
    cudaGetSymbolAddress((void**)&woh, c_woh); cudaGetSymbolAddress((void**)&wol, c_wol);
    cudaGetSymbolAddress((void**)&pqh, p_qh);  cudaGetSymbolAddress((void**)&pql, p_ql);
    cudaGetSymbolAddress((void**)&pkh, p_kh);  cudaGetSymbolAddress((void**)&pkl, p_kl);
    cudaGetSymbolAddress((void**)&pvh, p_vh);  cudaGetSymbolAddress((void**)&pvl, p_vl);
    cudaGetSymbolAddress((void**)&aoh, ao_h);  cudaGetSymbolAddress((void**)&aol, ao_l);
    cudaGetSymbolAddress((void**)&gmask, g_mask);

    cudaFuncSetAttribute(attn_mma, cudaFuncAttributeMaxDynamicSharedMemorySize,
                         ATTN_SMEM);
    cudaFuncSetAttribute(gemm_qkv, cudaFuncAttributeMaxDynamicSharedMemorySize,
                         GEMM_SMEM);
    cudaFuncSetAttribute(gemm_out, cudaFuncAttributeMaxDynamicSharedMemorySize,
                         GEMM_SMEM);

    sniff_mask_kernel<<<1, 256>>>((const unsigned char*)maskraw);
    norm_mask_kernel<<<NMASK / 256, 256>>>(maskraw);

    const int NIN = MROWS * EMB;
    const int NW  = EMB * EMB;
    conv_qkv<<<dim3(NIN / 4 / 256, 3), 256>>>(q, k, v, qh, ql, kh, kl, vh, vl);
    conv_w<<<dim3(NW / 4 / 256, 4), 256>>>(Wq, Wk, Wv, Wo,
                                           wqh, wql, wkh, wkl,
                                           wvh, wvl, woh, wol);

    dim3 ggrid3(EMB / GBN, MROWS / GBM, 3);   // (8, 64, 3)
    gemm_qkv<<<ggrid3, 256, GEMM_SMEM>>>(qh, ql, kh, kl, vh, vl,
                                         wqh, wql, wkh, wkl, wvh, wvl,
                                         pqh, pql, pkh, pkl, pvh, pvl);

    dim3 agrid(T_Q / AQ, NHEADS, BATCH);  // (16, 16, 4)
    attn_mma<<<agrid, 256, ATTN_SMEM>>>(pqh, pql, pkh, pkl, pvh, pvl, gmask,
                                        aoh, aol);

    dim3 ggrid(EMB / GBN, MROWS / GBM);   // (8, 64)
    gemm_out<<<ggrid, 256, GEMM_SMEM>>>(aoh, aol, woh, wol, out);
}

// round 11
// speedup vs baseline: 1.0308x; 1.0308x over previous
#include <cuda_runtime.h>
#include <cuda_bf16.h>
#include <math.h>
#include <stdint.h>

#define T_Q 2048
#define T_K 2048
#define BATCH 4
#define EMB 1024
#define NHEADS 16
#define HDIM 64
#define MROWS (T_Q * BATCH)   // 8192
#define NEGINF -1e9f
#define NMASK (BATCH * T_K)   // 8192

// ---------------------------------------------------------------------------
// Static device scratch. All bf16 hi/lo pairs.
// ---------------------------------------------------------------------------
__device__ __nv_bfloat16 c_qh[MROWS * EMB], c_ql[MROWS * EMB];
__device__ __nv_bfloat16 c_kh[MROWS * EMB], c_kl[MROWS * EMB];
__device__ __nv_bfloat16 c_vh[MROWS * EMB], c_vl[MROWS * EMB];
__device__ __nv_bfloat16 c_wqh[EMB * EMB], c_wql[EMB * EMB];
__device__ __nv_bfloat16 c_wkh[EMB * EMB], c_wkl[EMB * EMB];
__device__ __nv_bfloat16 c_wvh[EMB * EMB], c_wvl[EMB * EMB];
__device__ __nv_bfloat16 c_woh[EMB * EMB], c_wol[EMB * EMB];
__device__ __nv_bfloat16 p_qh[MROWS * EMB], p_ql[MROWS * EMB];
__device__ __nv_bfloat16 p_kh[MROWS * EMB], p_kl[MROWS * EMB];
__device__ __nv_bfloat16 p_vh[MROWS * EMB], p_vl[MROWS * EMB];
__device__ __nv_bfloat16 ao_h[MROWS * EMB], ao_l[MROWS * EMB];
__device__ __align__(16) unsigned char g_mask[NMASK];
__device__ int g_mask_kind;

// ===========================================================================
// helpers
// ===========================================================================
__device__ __forceinline__ uint32_t smem_u32(const void* p) {
    uint32_t a;
    asm("{ .reg .u64 t; cvta.to.shared.u64 t, %1; cvt.u32.u64 %0, t; }"
        : "=r"(a) : "l"(p));
    return a;
}
__device__ __forceinline__ void mma16816(float* c, const uint32_t* a,
                                         uint32_t b0, uint32_t b1) {
    asm volatile(
        "mma.sync.aligned.m16n8k16.row.col.f32.bf16.bf16.f32 "
        "{%0,%1,%2,%3}, {%4,%5,%6,%7}, {%8,%9}, {%0,%1,%2,%3};"
        : "+f"(c[0]), "+f"(c[1]), "+f"(c[2]), "+f"(c[3])
        : "r"(a[0]), "r"(a[1]), "r"(a[2]), "r"(a[3]), "r"(b0), "r"(b1));
}
__device__ __forceinline__ void ldsm_x4(uint32_t* r, uint32_t addr) {
    asm volatile("ldmatrix.sync.aligned.m8n8.x4.shared.b16 {%0,%1,%2,%3}, [%4];"
        : "=r"(r[0]), "=r"(r[1]), "=r"(r[2]), "=r"(r[3]) : "r"(addr));
}
__device__ __forceinline__ void ldsm_x4_t(uint32_t* r, uint32_t addr) {
    asm volatile("ldmatrix.sync.aligned.m8n8.x4.trans.shared.b16 {%0,%1,%2,%3}, [%4];"
        : "=r"(r[0]), "=r"(r[1]), "=r"(r[2]), "=r"(r[3]) : "r"(addr));
}
__device__ __forceinline__ void cp16(uint32_t sm, const void* g) {
    asm volatile("cp.async.cg.shared.global [%0], [%1], 16;" :: "r"(sm), "l"(g));
}
#define CP_COMMIT() asm volatile("cp.async.commit_group;" ::: "memory")
#define CP_WAIT(n)  asm volatile("cp.async.wait_group %0;" :: "n"(n) : "memory")

__device__ __forceinline__ void split1(float x, __nv_bfloat16& h, __nv_bfloat16& l) {
    h = __float2bfloat16(x);
    l = __float2bfloat16(x - __bfloat162float(h));
}
__device__ __forceinline__ uint32_t pack2(__nv_bfloat16 a, __nv_bfloat16 b) {
    return (uint32_t)__bfloat16_as_ushort(a) | ((uint32_t)__bfloat16_as_ushort(b) << 16);
}
__device__ __forceinline__ void split4(float4 v, uint2& hw, uint2& lw) {
    __nv_bfloat16 h0, h1, h2, h3, l0, l1, l2, l3;
    split1(v.x, h0, l0); split1(v.y, h1, l1);
    split1(v.z, h2, l2); split1(v.w, h3, l3);
    hw.x = pack2(h0, h1); hw.y = pack2(h2, h3);
    lw.x = pack2(l0, l1); lw.y = pack2(l2, l3);
}

// ===========================================================================
// batched fp32 -> bf16 hi/lo converters
// ===========================================================================
__global__ void conv_qkv(const float* __restrict__ q, const float* __restrict__ k,
                         const float* __restrict__ v,
                         __nv_bfloat16* __restrict__ qh, __nv_bfloat16* __restrict__ ql,
                         __nv_bfloat16* __restrict__ kh, __nv_bfloat16* __restrict__ kl,
                         __nv_bfloat16* __restrict__ vh, __nv_bfloat16* __restrict__ vl)
{
    const float* x = (blockIdx.y == 0) ? q : (blockIdx.y == 1) ? k : v;
    __nv_bfloat16* h = (blockIdx.y == 0) ? qh : (blockIdx.y == 1) ? kh : vh;
    __nv_bfloat16* l = (blockIdx.y == 0) ? ql : (blockIdx.y == 1) ? kl : vl;
    int i = (blockIdx.x * blockDim.x + threadIdx.x) * 4;
    float4 vv = *(const float4*)(x + i);
    uint2 hw, lw;
    split4(vv, hw, lw);
    *(uint2*)(h + i) = hw;
    *(uint2*)(l + i) = lw;
}

__global__ void conv_w(const float* __restrict__ w0, const float* __restrict__ w1,
                       const float* __restrict__ w2, const float* __restrict__ w3,
                       __nv_bfloat16* __restrict__ h0, __nv_bfloat16* __restrict__ l0,
                       __nv_bfloat16* __restrict__ h1, __nv_bfloat16* __restrict__ l1,
                       __nv_bfloat16* __restrict__ h2, __nv_bfloat16* __restrict__ l2,
                       __nv_bfloat16* __restrict__ h3, __nv_bfloat16* __restrict__ l3)
{
    int wsel = blockIdx.y;
    const float* x = (wsel == 0) ? w0 : (wsel == 1) ? w1 : (wsel == 2) ? w2 : w3;
    __nv_bfloat16* h = (wsel == 0) ? h0 : (wsel == 1) ? h1 : (wsel == 2) ? h2 : h3;
    __nv_bfloat16* l = (wsel == 0) ? l0 : (wsel == 1) ? l1 : (wsel == 2) ? l2 : l3;
    int i = (blockIdx.x * blockDim.x + threadIdx.x) * 4;
    float4 vv = *(const float4*)(x + i);
    uint2 hw, lw;
    split4(vv, hw, lw);
    *(uint2*)(h + i) = hw;
    *(uint2*)(l + i) = lw;
}

// ===========================================================================
// Mask dtype sniff + normalization (verified R3)
// ===========================================================================
__global__ void sniff_mask_kernel(const unsigned char* __restrict__ m)
{
    __shared__ int nz_off, nz_al;
    if (threadIdx.x == 0) { nz_off = 0; nz_al = 0; }
    __syncthreads();
    int loc_off = 0, loc_al = 0;
    for (int i = threadIdx.x; i < NMASK; i += blockDim.x) {
        unsigned char v = m[i];
        if (v) { if (i & 3) loc_off = 1; else loc_al = 1; }
    }
    if (loc_off) atomicOr(&nz_off, 1);
    if (loc_al)  atomicOr(&nz_al, 1);
    __syncthreads();
    if (threadIdx.x == 0) {
        int kind;
        if (!nz_off)     kind = 1;
        else if (!nz_al) kind = 2;
        else             kind = 0;
        g_mask_kind = kind;
    }
}

__global__ void norm_mask_kernel(const void* __restrict__ m)
{
    int i = blockIdx.x * blockDim.x + threadIdx.x;
    if (i >= NMASK) return;
    int kind = g_mask_kind;
    unsigned char r;
    if (kind == 1)      r = (((const int*)m)[i]   != 0);
    else if (kind == 2) r = (((const float*)m)[i] != 0.f);
    else                r = (((const unsigned char*)m)[i] != 0);
    g_mask[i] = r;
}

// ===========================================================================
// HMMA GEMM NT (R7-proven): C = A*B^T, bf16 hi/lo x3 chains,
// cp.async 2-stage (issue -> commit -> wait(1) -> sync -> compute -> sync).
// ===========================================================================
#define GBM 128
#define GBN 128
#define GBK 32
#define GSTR 40
#define ARR_SZ (128 * GSTR * 2)
#define STAGE_SZ (4 * ARR_SZ)
#define GEMM_SMEM (2 * STAGE_SZ)
#define O_AH 0
#define O_AL ARR_SZ
#define O_BH (2 * ARR_SZ)
#define O_BL (3 * ARR_SZ)

extern __shared__ char sm_raw[];

template <int OUTMODE>
__global__ __launch_bounds__(256, 2) void gemm_bf16(
    const __nv_bfloat16* __restrict__ Agh, const __nv_bfloat16* __restrict__ Agl,
    const __nv_bfloat16* __restrict__ Bgh, const __nv_bfloat16* __restrict__ Bgl,
    float* __restrict__ Cf,
    __nv_bfloat16* __restrict__ Ch, __nv_bfloat16* __restrict__ Cl)
{
    uint32_t sb = smem_u32(sm_raw);
    const int tid = threadIdx.x;
    const int wid = tid >> 5;
    const int lane = tid & 31;
    const int wm = (wid & 1) * 64;
    const int wn = (wid >> 1) * 32;
    const size_t rowA0 = (size_t)blockIdx.y * GBM;
    const size_t rowB0 = (size_t)blockIdx.x * GBN;

    const int carr = tid >> 6;
    const int crow0 = (tid & 63) >> 1;
    const int cseg = (tid & 1) << 1;
    const __nv_bfloat16* gbase[4] = {
        Agh + rowA0 * EMB, Agl + rowA0 * EMB,
        Bgh + rowB0 * EMB, Bgl + rowB0 * EMB };
    const __nv_bfloat16* mygb = gbase[carr];
    const uint32_t myarr = sb + carr * ARR_SZ;

    float acc[4][4][4];
#pragma unroll
    for (int mt = 0; mt < 4; mt++)
#pragma unroll
        for (int nt = 0; nt < 4; nt++)
#pragma unroll
            for (int e = 0; e < 4; e++) acc[mt][nt][e] = 0.f;

    const int NCH = EMB / GBK;   // 32

#pragma unroll
    for (int rr = 0; rr < 4; rr++) {
        int row = crow0 + rr * 32;
        uint32_t smaddr = myarr + row * (GSTR * 2) + cseg * 16;
        const void* g = mygb + (size_t)row * EMB + cseg * 8;
        cp16(smaddr, g);
        cp16(smaddr + 16, (const char*)g + 16);
    }
    CP_COMMIT();

    for (int c = 0; c < NCH; c++) {
        if (c + 1 < NCH) {
            const int kt = (c + 1) * GBK;
            const uint32_t stb = myarr + ((c + 1) & 1) * STAGE_SZ;
#pragma unroll
            for (int rr = 0; rr < 4; rr++) {
                int row = crow0 + rr * 32;
                uint32_t smaddr = stb + row * (GSTR * 2) + cseg * 16;
                const void* g = mygb + (size_t)row * EMB + kt + cseg * 8;
                cp16(smaddr, g);
                cp16(smaddr + 16, (const char*)g + 16);
            }
            CP_COMMIT();
            CP_WAIT(1);
        } else {
            CP_WAIT(0);
        }
        __syncthreads();

        const uint32_t base = sb + (uint32_t)(c & 1) * STAGE_SZ;
        const uint32_t lrow = lane & 15;
        const uint32_t lcol = (lane >> 4) << 3;
#pragma unroll
        for (int kk = 0; kk < GBK; kk += 16) {
            uint32_t af[4][4];
#pragma unroll
            for (int mt = 0; mt < 4; mt++) {
                uint32_t addr = base + O_AH +
                    (uint32_t)(((wm + mt * 16 + lrow) * GSTR + kk + lcol) * 2);
                ldsm_x4(af[mt], addr);
            }
            uint32_t b0h[4], b1h[4], b0l[4], b1l[4];
#pragma unroll
            for (int g = 0; g < 2; g++) {
                uint32_t roff = (uint32_t)(((wn + g * 16 + lrow) * GSTR + kk + lcol) * 2);
                uint32_t r4[4];
                ldsm_x4(r4, base + O_BH + roff);
                b0h[2 * g] = r4[0]; b0h[2 * g + 1] = r4[1];
                b1h[2 * g] = r4[2]; b1h[2 * g + 1] = r4[3];
                ldsm_x4(r4, base + O_BL + roff);
                b0l[2 * g] = r4[0]; b0l[2 * g + 1] = r4[1];
                b1l[2 * g] = r4[2]; b1l[2 * g + 1] = r4[3];
            }
#pragma unroll
            for (int mt = 0; mt < 4; mt++)
#pragma unroll
                for (int nt = 0; nt < 4; nt++) {
                    mma16816(acc[mt][nt], af[mt], b0h[nt], b1h[nt]);
                    mma16816(acc[mt][nt], af[mt], b0l[nt], b1l[nt]);
                }
#pragma unroll
            for (int mt = 0; mt < 4; mt++) {
                uint32_t addr = base + O_AL +
                    (uint32_t)(((wm + mt * 16 + lrow) * GSTR + kk + lcol) * 2);
                ldsm_x4(af[mt], addr);
            }
#pragma unroll
            for (int mt = 0; mt < 4; mt++)
#pragma unroll
                for (int nt = 0; nt < 4; nt++)
                    mma16816(acc[mt][nt], af[mt], b0h[nt], b1h[nt]);
        }
        __syncthreads();
    }

#pragma unroll
    for (int mt = 0; mt < 4; mt++) {
        size_t r0 = rowA0 + wm + mt * 16 + (lane >> 2);
        size_t r1 = r0 + 8;
#pragma unroll
        for (int nt = 0; nt < 4; nt++) {
            size_t cc = rowB0 + wn + nt * 8 + (lane & 3) * 2;
            if (OUTMODE == 0) {
                *(float2*)(Cf + r0 * EMB + cc) = make_float2(acc[mt][nt][0], acc[mt][nt][1]);
                *(float2*)(Cf + r1 * EMB + cc) = make_float2(acc[mt][nt][2], acc[mt][nt][3]);
            } else {
                __nv_bfloat16 h0, l0, h1, l1;
                split1(acc[mt][nt][0], h0, l0);
                split1(acc[mt][nt][1], h1, l1);
                *(uint32_t*)(Ch + r0 * EMB + cc) = pack2(h0, h1);
                *(uint32_t*)(Cl + r0 * EMB + cc) = pack2(l0, l1);
                split1(acc[mt][nt][2], h0, l0);
                split1(acc[mt][nt][3], h1, l1);
                *(uint32_t*)(Ch + r1 * EMB + cc) = pack2(h0, h1);
                *(uint32_t*)(Cl + r1 * EMB + cc) = pack2(l0, l1);
            }
        }
    }
}

// ===========================================================================
// FA2 flash attention (R7 body, AK=128 staging): 128 q/CTA, warp = 16q x 64k
// per pass, TWO passes per 128-key stage -> half the wait/barrier points.
// Register softmax, register-resident P, 2-stage cp.async (R7 schedule).
// ===========================================================================
#define AQ 128
#define AK 128
#define ASTR 72
#define AROWB (ASTR * 2)       // 144 B per smem row
#define KVROWS (AK * AROWB)    // 18432 B per K/V array per stage
#define ANT (T_K / AK)         // 16 stages

struct AttnSmem {
    __nv_bfloat16 Qh[AQ][ASTR], Ql[AQ][ASTR];              // 36,864
    __nv_bfloat16 Kh[2][AK][ASTR], Kl[2][AK][ASTR];        // 73,728
    __nv_bfloat16 Vh[2][AK][ASTR], Vl[2][AK][ASTR];        // 73,728
    unsigned char msk[2][AK];                              // 256
};
#define ATTN_SMEM ((int)sizeof(AttnSmem))

__global__ __launch_bounds__(256) void attn_mma(
    const __nv_bfloat16* __restrict__ Qhg, const __nv_bfloat16* __restrict__ Qlg,
    const __nv_bfloat16* __restrict__ Khg, const __nv_bfloat16* __restrict__ Klg,
    const __nv_bfloat16* __restrict__ Vhg, const __nv_bfloat16* __restrict__ Vlg,
    const unsigned char* __restrict__ mask,
    __nv_bfloat16* __restrict__ Ohg, __nv_bfloat16* __restrict__ Olg)
{
    AttnSmem& s = *reinterpret_cast<AttnSmem*>(sm_raw);
    const int b  = blockIdx.z;
    const int h  = blockIdx.y;
    const int qt = blockIdx.x;
    const int tid = threadIdx.x;
    const int wid = tid >> 5;
    const int lane = tid & 31;
    const size_t headoff = (size_t)h * HDIM;

    const uint32_t sqh = smem_u32(&s.Qh[0][0]);
    const uint32_t sql = smem_u32(&s.Ql[0][0]);
    const uint32_t skh = smem_u32(&s.Kh[0][0][0]);
    const uint32_t skl = smem_u32(&s.Kl[0][0][0]);
    const uint32_t svh = smem_u32(&s.Vh[0][0][0]);
    const uint32_t svl = smem_u32(&s.Vl[0][0][0]);
    const uint32_t smk = smem_u32(&s.msk[0][0]);

    // --- Q tile -> smem ---
#pragma unroll
    for (int t = 0; t < 4; t++) {
        int i = tid + t * 256;
        int r = i >> 3, seg = i & 7;
        size_t gi = ((size_t)(qt * AQ + r) * BATCH + b) * EMB + headoff + seg * 8;
        *(uint4*)((char*)&s.Qh[r][0] + seg * 16) = *(const uint4*)(Qhg + gi);
        *(uint4*)((char*)&s.Ql[r][0] + seg * 16) = *(const uint4*)(Qlg + gi);
    }

    // --- cp.async assignment: tid>>6 -> array; 2 rows per thread ---
    const int ca = tid >> 6;
    const int crow = tid & 63;
    const __nv_bfloat16* casrc = (ca == 0) ? Khg : (ca == 1) ? Klg
                                : (ca == 2) ? Vhg : Vlg;
    const uint32_t cadst = (ca == 0) ? skh : (ca == 1) ? skl
                          : (ca == 2) ? svh : svl;

    // prefetch k-stage 0
    {
#pragma unroll
        for (int rr = 0; rr < 2; rr++) {
            int row = crow + rr * 64;
            size_t gi = ((size_t)row * BATCH + b) * EMB + headoff;
            const char* g = (const char*)(casrc + gi);
            uint32_t d = cadst + row * AROWB;
#pragma unroll
            for (int seg = 0; seg < 8; seg++) cp16(d + seg * 16, g + seg * 16);
        }
        if (tid < 8) cp16(smk + tid * 16, mask + (size_t)b * T_K + tid * 16);
    }
    CP_COMMIT();

    float m0 = -INFINITY, m1 = -INFINITY, l0 = 0.f, l1 = 0.f;
    float o[8][4];
#pragma unroll
    for (int nt = 0; nt < 8; nt++)
#pragma unroll
        for (int e = 0; e < 4; e++) o[nt][e] = 0.f;

    const uint32_t lrow = lane & 15;
    const uint32_t lcol = (lane >> 4) << 3;

    for (int kt = 0; kt < ANT; kt++) {
        if (kt + 1 < ANT) {
            int st2 = (kt + 1) & 1;
#pragma unroll
            for (int rr = 0; rr < 2; rr++) {
                int row = crow + rr * 64;
                size_t gi = ((size_t)((kt + 1) * AK + row) * BATCH + b) * EMB + headoff;
                const char* g = (const char*)(casrc + gi);
                uint32_t d = cadst + st2 * KVROWS + row * AROWB;
#pragma unroll
                for (int seg = 0; seg < 8; seg++) cp16(d + seg * 16, g + seg * 16);
            }
            if (tid < 8)
                cp16(smk + st2 * AK + tid * 16,
                     mask + (size_t)b * T_K + (kt + 1) * AK + tid * 16);
            CP_COMMIT();
            CP_WAIT(1);
        } else {
            CP_WAIT(0);
        }
        __syncthreads();

        const int st = kt & 1;

        // two 64-key passes over this 128-key stage
#pragma unroll
        for (int p = 0; p < 2; p++) {
            const uint32_t koff = (uint32_t)(p * 64) * AROWB;
            const uint32_t kbh = skh + st * KVROWS + koff;
            const uint32_t kbl = skl + st * KVROWS + koff;
            const uint32_t vbh = svh + st * KVROWS + koff;
            const uint32_t vbl = svl + st * KVROWS + koff;
            const unsigned char* mrow = &s.msk[st][p * 64];

            // ---- S = Q K^T (warp: 16q x 64k), 3 chains ----
            float sc[8][4];
#pragma unroll
            for (int nt = 0; nt < 8; nt++)
#pragma unroll
                for (int e = 0; e < 4; e++) sc[nt][e] = 0.f;

#pragma unroll
            for (int kk = 0; kk < 4; kk++) {
                uint32_t aoff = (uint32_t)(((wid * 16 + lrow) * ASTR + kk * 16 + lcol) * 2);
                uint32_t ah[4], al[4];
                ldsm_x4(ah, sqh + aoff);
                ldsm_x4(al, sql + aoff);
                uint32_t b0h[8], b1h[8], b0l[8], b1l[8];
#pragma unroll
                for (int g = 0; g < 4; g++) {
                    uint32_t roff = (uint32_t)(((g * 16 + lrow) * ASTR + kk * 16 + lcol) * 2);
                    uint32_t r4[4];
                    ldsm_x4(r4, kbh + roff);
                    b0h[2*g] = r4[0]; b0h[2*g+1] = r4[1];
                    b1h[2*g] = r4[2]; b1h[2*g+1] = r4[3];
                    ldsm_x4(r4, kbl + roff);
                    b0l[2*g] = r4[0]; b0l[2*g+1] = r4[1];
                    b1l[2*g] = r4[2]; b1l[2*g+1] = r4[3];
                }
#pragma unroll
                for (int nt = 0; nt < 8; nt++) {
                    mma16816(sc[nt], ah, b0h[nt], b1h[nt]);
                    mma16816(sc[nt], ah, b0l[nt], b1l[nt]);
                    mma16816(sc[nt], al, b0h[nt], b1h[nt]);
                }
            }

            // ---- register softmax ----
            float tm0 = -INFINITY, tm1 = -INFINITY;
#pragma unroll
            for (int nt = 0; nt < 8; nt++) {
                int k0 = nt * 8 + (lane & 3) * 2;
                bool mk0 = mrow[k0] != 0, mk1 = mrow[k0 + 1] != 0;
                sc[nt][0] = mk0 ? NEGINF : sc[nt][0] * 0.125f;
                sc[nt][1] = mk1 ? NEGINF : sc[nt][1] * 0.125f;
                sc[nt][2] = mk0 ? NEGINF : sc[nt][2] * 0.125f;
                sc[nt][3] = mk1 ? NEGINF : sc[nt][3] * 0.125f;
                tm0 = fmaxf(tm0, fmaxf(sc[nt][0], sc[nt][1]));
                tm1 = fmaxf(tm1, fmaxf(sc[nt][2], sc[nt][3]));
            }
            tm0 = fmaxf(tm0, __shfl_xor_sync(0xffffffffu, tm0, 1));
            tm0 = fmaxf(tm0, __shfl_xor_sync(0xffffffffu, tm0, 2));
            tm1 = fmaxf(tm1, __shfl_xor_sync(0xffffffffu, tm1, 1));
            tm1 = fmaxf(tm1, __shfl_xor_sync(0xffffffffu, tm1, 2));

            float mn0 = fmaxf(m0, tm0), mn1 = fmaxf(m1, tm1);
            float al0 = __expf(m0 - mn0), al1 = __expf(m1 - mn1);
            m0 = mn0; m1 = mn1;

            float ts0 = 0.f, ts1 = 0.f;
            uint32_t pfh[4][4], pfl[4][4];
#pragma unroll
            for (int nt = 0; nt < 8; nt++) {
                float p0 = __expf(sc[nt][0] - mn0);
                float p1 = __expf(sc[nt][1] - mn0);
                float p2 = __expf(sc[nt][2] - mn1);
                float p3 = __expf(sc[nt][3] - mn1);
                ts0 += p0 + p1;
                ts1 += p2 + p3;
                __nv_bfloat16 h0, lo0, h1, lo1;
                int t = nt >> 1, half = (nt & 1) * 2;
                split1(p0, h0, lo0); split1(p1, h1, lo1);
                pfh[t][half + 0] = pack2(h0, h1);
                pfl[t][half + 0] = pack2(lo0, lo1);
                split1(p2, h0, lo0); split1(p3, h1, lo1);
                pfh[t][half + 1] = pack2(h0, h1);
                pfl[t][half + 1] = pack2(lo0, lo1);
            }
            ts0 += __shfl_xor_sync(0xffffffffu, ts0, 1);
            ts0 += __shfl_xor_sync(0xffffffffu, ts0, 2);
            ts1 += __shfl_xor_sync(0xffffffffu, ts1, 1);
            ts1 += __shfl_xor_sync(0xffffffffu, ts1, 2);
            l0 = l0 * al0 + ts0;
            l1 = l1 * al1 + ts1;

#pragma unroll
            for (int nt = 0; nt < 8; nt++) {
                o[nt][0] *= al0; o[nt][1] *= al0;
                o[nt][2] *= al1; o[nt][3] *= al1;
            }

            // ---- O += P V (warp: 16q x 64d), 3 chains ----
#pragma unroll
            for (int t = 0; t < 4; t++) {
                uint32_t b0h[8], b1h[8], b0l[8], b1l[8];
#pragma unroll
                for (int g = 0; g < 4; g++) {
                    uint32_t vrow = (uint32_t)(t * 16 + (lane & 7) + ((lane >> 3) & 1) * 8);
                    uint32_t vcol = (uint32_t)(g * 16 + ((lane >> 4) << 3));
                    uint32_t roff = (vrow * ASTR + vcol) * 2;
                    uint32_t r4[4];
                    ldsm_x4_t(r4, vbh + roff);
                    b0h[2*g] = r4[0]; b1h[2*g] = r4[1];
                    b0h[2*g+1] = r4[2]; b1h[2*g+1] = r4[3];
                    ldsm_x4_t(r4, vbl + roff);
                    b0l[2*g] = r4[0]; b1l[2*g] = r4[1];
                    b0l[2*g+1] = r4[2]; b1l[2*g+1] = r4[3];
                }
#pragma unroll
                for (int nt = 0; nt < 8; nt++) {
                    mma16816(o[nt], pfh[t], b0h[nt], b1h[nt]);
                    mma16816(o[nt], pfh[t], b0l[nt], b1l[nt]);
                    mma16816(o[nt], pfl[t], b0h[nt], b1h[nt]);
                }
            }
        }
    }

    // ---- finalize: /l, write bf16 hi/lo AO at (t, b, e) ----
    float inv0 = 1.f / l0;
    float inv1 = 1.f / l1;
    const int r0 = wid * 16 + (lane >> 2);
    const int r1 = r0 + 8;
    size_t tg0 = (size_t)(qt * AQ + r0) * BATCH + b;
    size_t tg1 = (size_t)(qt * AQ + r1) * BATCH + b;
#pragma unroll
    for (int nt = 0; nt < 8; nt++) {
        size_t d0 = nt * 8 + (lane & 3) * 2;
        __nv_bfloat16 h0, lo0, h1, lo1;
        split1(o[nt][0] * inv0, h0, lo0);
        split1(o[nt][1] * inv0, h1, lo1);
        *(uint32_t*)(Ohg + tg0 * EMB + headoff + d0) = pack2(h0, h1);
        *(uint32_t*)(Olg + tg0 * EMB + headoff + d0) = pack2(lo0, lo1);
        split1(o[nt][2] * inv1, h0, lo0);
        split1(o[nt][3] * inv1, h1, lo1);
        *(uint32_t*)(Ohg + tg1 * EMB + headoff + d0) = pack2(h0, h1);
        *(uint32_t*)(Olg + tg1 * EMB + headoff + d0) = pack2(lo0, lo1);
    }
}

// ===========================================================================
// Launch
// ===========================================================================
extern "C" void kernel_launch(void* const* d_in, const int* in_sizes, int n_in,
                              void* d_out, int out_size)
{
    const float* q  = (const float*)d_in[0];
    const float* k  = (const float*)d_in[1];
    const float* v  = (const float*)d_in[2];
    const void*  maskraw = d_in[3];
    const float* Wq = (const float*)d_in[4];
    const float* Wk = (const float*)d_in[5];
    const float* Wv = (const float*)d_in[6];
    const float* Wo = (const float*)d_in[7];
    float* out = (float*)d_out;

    __nv_bfloat16 *qh, *ql, *kh, *kl, *vh, *vl;
    __nv_bfloat16 *wqh, *wql, *wkh, *wkl, *wvh, *wvl, *woh, *wol;
    __nv_bfloat16 *pqh, *pql, *pkh, *pkl, *pvh, *pvl, *aoh, *aol;
    unsigned char* gmask;
    cudaGetSymbolAddress((void**)&qh, c_qh);  cudaGetSymbolAddress((void**)&ql, c_ql);
    cudaGetSymbolAddress((void**)&kh, c_kh);  cudaGetSymbolAddress((void**)&kl, c_kl);
    cudaGetSymbolAddress((void**)&vh, c_vh);  cudaGetSymbolAddress((void**)&vl, c_vl);
    cudaGetSymbolAddress((void**)&wqh, c_wqh); cudaGetSymbolAddress((void**)&wql, c_wql);
    cudaGetSymbolAddress((void**)&wkh, c_wkh); cudaGetSymbolAddress((void**)&wkl, c_wkl);
    cudaGetSymbolAddress((void**)&wvh, c_wvh); cudaGetSymbolAddress((void**)&wvl, c_wvl);
    cudaGetSymbolAddress((void**)&woh, c_woh); cudaGetSymbolAddress((void**)&wol, c_wol);
    cudaGetSymbolAddress((void**)&pqh, p_qh);  cudaGetSymbolAddress((void**)&pql, p_ql);
    cudaGetSymbolAddress((void**)&pkh, p_kh);  cudaGetSymbolAddress((void**)&pkl, p_kl);
    cudaGetSymbolAddress((void**)&pvh, p_vh);  cudaGetSymbolAddress((void**)&pvl, p_vl);
    cudaGetSymbolAddress((void**)&aoh, ao_h);  cudaGetSymbolAddress((void**)&aol, ao_l);
    cudaGetSymbolAddress((void**)&gmask, g_mask);

    cudaFuncSetAttribute(attn_mma, cudaFuncAttributeMaxDynamicSharedMemorySize,
                         ATTN_SMEM);
    cudaFuncSetAttribute(gemm_bf16<0>, cudaFuncAttributeMaxDynamicSharedMemorySize,
                         GEMM_SMEM);
    cudaFuncSetAttribute(gemm_bf16<1>, cudaFuncAttributeMaxDynamicSharedMemorySize,
                         GEMM_SMEM);

    sniff_mask_kernel<<<1, 256>>>((const unsigned char*)maskraw);
    norm_mask_kernel<<<NMASK / 256, 256>>>(maskraw);

    const int NIN = MROWS * EMB;
    const int NW  = EMB * EMB;
    conv_qkv<<<dim3(NIN / 4 / 256, 3), 256>>>(q, k, v, qh, ql, kh, kl, vh, vl);
    conv_w<<<dim3(NW / 4 / 256, 4), 256>>>(Wq, Wk, Wv, Wo,
                                           wqh, wql, wkh, wkl,
                                           wvh, wvl, woh, wol);

    dim3 ggrid(EMB / GBN, MROWS / GBM);   // (8, 64)
    gemm_bf16<1><<<ggrid, 256, GEMM_SMEM>>>(qh, ql, wqh, wql, nullptr, pqh, pql);
    gemm_bf16<1><<<ggrid, 256, GEMM_SMEM>>>(kh, kl, wkh, wkl, nullptr, pkh, pkl);
    gemm_bf16<1><<<ggrid, 256, GEMM_SMEM>>>(vh, vl, wvh, wvl, nullptr, pvh, pvl);

    dim3 agrid(T_Q / AQ, NHEADS, BATCH);  // (16, 16, 4)
    attn_mma<<<agrid, 256, ATTN_SMEM>>>(pqh, pql, pkh, pkl, pvh, pvl, gmask,
                                        aoh, aol);

    gemm_bf16<0><<<ggrid, 256, GEMM_SMEM>>>(aoh, aol, woh, wol, out,
                                            nullptr, nullptr);
}

// round 14
// speedup vs baseline: 1.0949x; 1.0622x over previous
#include <cuda_runtime.h>
#include <cuda_bf16.h>
#include <math.h>
#include <stdint.h>

#define T_Q 2048
#define T_K 2048
#define BATCH 4
#define EMB 1024
#define NHEADS 16
#define HDIM 64
#define MROWS (T_Q * BATCH)   // 8192
#define NEGINF -1e9f
#define NMASK (BATCH * T_K)   // 8192

// ---------------------------------------------------------------------------
// Static device scratch. All bf16 hi/lo pairs.
// ---------------------------------------------------------------------------
__device__ __nv_bfloat16 c_qh[MROWS * EMB], c_ql[MROWS * EMB];
__device__ __nv_bfloat16 c_kh[MROWS * EMB], c_kl[MROWS * EMB];
__device__ __nv_bfloat16 c_vh[MROWS * EMB], c_vl[MROWS * EMB];
__device__ __nv_bfloat16 c_wqh[EMB * EMB], c_wql[EMB * EMB];
__device__ __nv_bfloat16 c_wkh[EMB * EMB], c_wkl[EMB * EMB];
__device__ __nv_bfloat16 c_wvh[EMB * EMB], c_wvl[EMB * EMB];
__device__ __nv_bfloat16 c_woh[EMB * EMB], c_wol[EMB * EMB];
__device__ __nv_bfloat16 p_qh[MROWS * EMB], p_ql[MROWS * EMB];
__device__ __nv_bfloat16 p_kh[MROWS * EMB], p_kl[MROWS * EMB];
__device__ __nv_bfloat16 p_vh[MROWS * EMB], p_vl[MROWS * EMB];
__device__ __nv_bfloat16 ao_h[MROWS * EMB], ao_l[MROWS * EMB];
__device__ __align__(16) unsigned char g_mask[NMASK];
__device__ int g_mask_kind;

// ===========================================================================
// helpers
// ===========================================================================
__device__ __forceinline__ uint32_t smem_u32(const void* p) {
    uint32_t a;
    asm("{ .reg .u64 t; cvta.to.shared.u64 t, %1; cvt.u32.u64 %0, t; }"
        : "=r"(a) : "l"(p));
    return a;
}
__device__ __forceinline__ void mma16816(float* c, const uint32_t* a,
                                         uint32_t b0, uint32_t b1) {
    asm volatile(
        "mma.sync.aligned.m16n8k16.row.col.f32.bf16.bf16.f32 "
        "{%0,%1,%2,%3}, {%4,%5,%6,%7}, {%8,%9}, {%0,%1,%2,%3};"
        : "+f"(c[0]), "+f"(c[1]), "+f"(c[2]), "+f"(c[3])
        : "r"(a[0]), "r"(a[1]), "r"(a[2]), "r"(a[3]), "r"(b0), "r"(b1));
}
__device__ __forceinline__ void ldsm_x4(uint32_t* r, uint32_t addr) {
    asm volatile("ldmatrix.sync.aligned.m8n8.x4.shared.b16 {%0,%1,%2,%3}, [%4];"
        : "=r"(r[0]), "=r"(r[1]), "=r"(r[2]), "=r"(r[3]) : "r"(addr));
}
__device__ __forceinline__ void ldsm_x4_t(uint32_t* r, uint32_t addr) {
    asm volatile("ldmatrix.sync.aligned.m8n8.x4.trans.shared.b16 {%0,%1,%2,%3}, [%4];"
        : "=r"(r[0]), "=r"(r[1]), "=r"(r[2]), "=r"(r[3]) : "r"(addr));
}
__device__ __forceinline__ void cp16(uint32_t sm, const void* g) {
    asm volatile("cp.async.cg.shared.global [%0], [%1], 16;" :: "r"(sm), "l"(g));
}
#define CP_COMMIT() asm volatile("cp.async.commit_group;" ::: "memory")
#define CP_WAIT(n)  asm volatile("cp.async.wait_group %0;" :: "n"(n) : "memory")

__device__ __forceinline__ void split1(float x, __nv_bfloat16& h, __nv_bfloat16& l) {
    h = __float2bfloat16(x);
    l = __float2bfloat16(x - __bfloat162float(h));
}
__device__ __forceinline__ uint32_t pack2(__nv_bfloat16 a, __nv_bfloat16 b) {
    return (uint32_t)__bfloat16_as_ushort(a) | ((uint32_t)__bfloat16_as_ushort(b) << 16);
}
__device__ __forceinline__ void split4(float4 v, uint2& hw, uint2& lw) {
    __nv_bfloat16 h0, h1, h2, h3, l0, l1, l2, l3;
    split1(v.x, h0, l0); split1(v.y, h1, l1);
    split1(v.z, h2, l2); split1(v.w, h3, l3);
    hw.x = pack2(h0, h1); hw.y = pack2(h2, h3);
    lw.x = pack2(l0, l1); lw.y = pack2(l2, l3);
}

// ===========================================================================
// batched fp32 -> bf16 hi/lo converters
// ===========================================================================
__global__ void conv_qkv(const float* __restrict__ q, const float* __restrict__ k,
                         const float* __restrict__ v,
                         __nv_bfloat16* __restrict__ qh, __nv_bfloat16* __restrict__ ql,
                         __nv_bfloat16* __restrict__ kh, __nv_bfloat16* __restrict__ kl,
                         __nv_bfloat16* __restrict__ vh, __nv_bfloat16* __restrict__ vl)
{
    const float* x = (blockIdx.y == 0) ? q : (blockIdx.y == 1) ? k : v;
    __nv_bfloat16* h = (blockIdx.y == 0) ? qh : (blockIdx.y == 1) ? kh : vh;
    __nv_bfloat16* l = (blockIdx.y == 0) ? ql : (blockIdx.y == 1) ? kl : vl;
    int i = (blockIdx.x * blockDim.x + threadIdx.x) * 4;
    float4 vv = *(const float4*)(x + i);
    uint2 hw, lw;
    split4(vv, hw, lw);
    *(uint2*)(h + i) = hw;
    *(uint2*)(l + i) = lw;
}

__global__ void conv_w(const float* __restrict__ w0, const float* __restrict__ w1,
                       const float* __restrict__ w2, const float* __restrict__ w3,
                       __nv_bfloat16* __restrict__ h0, __nv_bfloat16* __restrict__ l0,
                       __nv_bfloat16* __restrict__ h1, __nv_bfloat16* __restrict__ l1,
                       __nv_bfloat16* __restrict__ h2, __nv_bfloat16* __restrict__ l2,
                       __nv_bfloat16* __restrict__ h3, __nv_bfloat16* __restrict__ l3)
{
    int wsel = blockIdx.y;
    const float* x = (wsel == 0) ? w0 : (wsel == 1) ? w1 : (wsel == 2) ? w2 : w3;
    __nv_bfloat16* h = (wsel == 0) ? h0 : (wsel == 1) ? h1 : (wsel == 2) ? h2 : h3;
    __nv_bfloat16* l = (wsel == 0) ? l0 : (wsel == 1) ? l1 : (wsel == 2) ? l2 : l3;
    int i = (blockIdx.x * blockDim.x + threadIdx.x) * 4;
    float4 vv = *(const float4*)(x + i);
    uint2 hw, lw;
    split4(vv, hw, lw);
    *(uint2*)(h + i) = hw;
    *(uint2*)(l + i) = lw;
}

// ===========================================================================
// Mask dtype sniff + normalization (verified R3)
// ===========================================================================
__global__ void sniff_mask_kernel(const unsigned char* __restrict__ m)
{
    __shared__ int nz_off, nz_al;
    if (threadIdx.x == 0) { nz_off = 0; nz_al = 0; }
    __syncthreads();
    int loc_off = 0, loc_al = 0;
    for (int i = threadIdx.x; i < NMASK; i += blockDim.x) {
        unsigned char v = m[i];
        if (v) { if (i & 3) loc_off = 1; else loc_al = 1; }
    }
    if (loc_off) atomicOr(&nz_off, 1);
    if (loc_al)  atomicOr(&nz_al, 1);
    __syncthreads();
    if (threadIdx.x == 0) {
        int kind;
        if (!nz_off)     kind = 1;
        else if (!nz_al) kind = 2;
        else             kind = 0;
        g_mask_kind = kind;
    }
}

__global__ void norm_mask_kernel(const void* __restrict__ m)
{
    int i = blockIdx.x * blockDim.x + threadIdx.x;
    if (i >= NMASK) return;
    int kind = g_mask_kind;
    unsigned char r;
    if (kind == 1)      r = (((const int*)m)[i]   != 0);
    else if (kind == 2) r = (((const float*)m)[i] != 0.f);
    else                r = (((const unsigned char*)m)[i] != 0);
    g_mask[i] = r;
}

// ===========================================================================
// HMMA GEMM NT: C = A*B^T, bf16 hi/lo x3 chains,
// cp.async 2-stage (issue -> commit -> wait(1) -> sync -> compute -> sync).
// ===========================================================================
#define GBM 128
#define GBN 128
#define GBK 32
#define GSTR 40
#define ARR_SZ (128 * GSTR * 2)
#define STAGE_SZ (4 * ARR_SZ)
#define GEMM_SMEM (2 * STAGE_SZ)
#define O_AH 0
#define O_AL ARR_SZ
#define O_BH (2 * ARR_SZ)
#define O_BL (3 * ARR_SZ)

extern __shared__ char sm_raw[];

template <int OUTMODE>
__global__ __launch_bounds__(256, 2) void gemm_bf16(
    const __nv_bfloat16* __restrict__ Agh, const __nv_bfloat16* __restrict__ Agl,
    const __nv_bfloat16* __restrict__ Bgh, const __nv_bfloat16* __restrict__ Bgl,
    float* __restrict__ Cf,
    __nv_bfloat16* __restrict__ Ch, __nv_bfloat16* __restrict__ Cl)
{
    uint32_t sb = smem_u32(sm_raw);
    const int tid = threadIdx.x;
    const int wid = tid >> 5;
    const int lane = tid & 31;
    const int wm = (wid & 1) * 64;
    const int wn = (wid >> 1) * 32;
    const size_t rowA0 = (size_t)blockIdx.y * GBM;
    const size_t rowB0 = (size_t)blockIdx.x * GBN;

    const int carr = tid >> 6;
    const int crow0 = (tid & 63) >> 1;
    const int cseg = (tid & 1) << 1;
    const __nv_bfloat16* gbase[4] = {
        Agh + rowA0 * EMB, Agl + rowA0 * EMB,
        Bgh + rowB0 * EMB, Bgl + rowB0 * EMB };
    const __nv_bfloat16* mygb = gbase[carr];
    const uint32_t myarr = sb + carr * ARR_SZ;

    float acc[4][4][4];
#pragma unroll
    for (int mt = 0; mt < 4; mt++)
#pragma unroll
        for (int nt = 0; nt < 4; nt++)
#pragma unroll
            for (int e = 0; e < 4; e++) acc[mt][nt][e] = 0.f;

    const int NCH = EMB / GBK;   // 32

#pragma unroll
    for (int rr = 0; rr < 4; rr++) {
        int row = crow0 + rr * 32;
        uint32_t smaddr = myarr + row * (GSTR * 2) + cseg * 16;
        const void* g = mygb + (size_t)row * EMB + cseg * 8;
        cp16(smaddr, g);
        cp16(smaddr + 16, (const char*)g + 16);
    }
    CP_COMMIT();

    for (int c = 0; c < NCH; c++) {
        if (c + 1 < NCH) {
            const int kt = (c + 1) * GBK;
            const uint32_t stb = myarr + ((c + 1) & 1) * STAGE_SZ;
#pragma unroll
            for (int rr = 0; rr < 4; rr++) {
                int row = crow0 + rr * 32;
                uint32_t smaddr = stb + row * (GSTR * 2) + cseg * 16;
                const void* g = mygb + (size_t)row * EMB + kt + cseg * 8;
                cp16(smaddr, g);
                cp16(smaddr + 16, (const char*)g + 16);
            }
            CP_COMMIT();
            CP_WAIT(1);
        } else {
            CP_WAIT(0);
        }
        __syncthreads();

        const uint32_t base = sb + (uint32_t)(c & 1) * STAGE_SZ;
        const uint32_t lrow = lane & 15;
        const uint32_t lcol = (lane >> 4) << 3;
#pragma unroll
        for (int kk = 0; kk < GBK; kk += 16) {
            uint32_t af[4][4];
#pragma unroll
            for (int mt = 0; mt < 4; mt++) {
                uint32_t addr = base + O_AH +
                    (uint32_t)(((wm + mt * 16 + lrow) * GSTR + kk + lcol) * 2);
                ldsm_x4(af[mt], addr);
            }
            uint32_t b0h[4], b1h[4], b0l[4], b1l[4];
#pragma unroll
            for (int g = 0; g < 2; g++) {
                uint32_t roff = (uint32_t)(((wn + g * 16 + lrow) * GSTR + kk + lcol) * 2);
                uint32_t r4[4];
                ldsm_x4(r4, base + O_BH + roff);
                b0h[2 * g] = r4[0]; b0h[2 * g + 1] = r4[1];
                b1h[2 * g] = r4[2]; b1h[2 * g + 1] = r4[3];
                ldsm_x4(r4, base + O_BL + roff);
                b0l[2 * g] = r4[0]; b0l[2 * g + 1] = r4[1];
                b1l[2 * g] = r4[2]; b1l[2 * g + 1] = r4[3];
            }
#pragma unroll
            for (int mt = 0; mt < 4; mt++)
#pragma unroll
                for (int nt = 0; nt < 4; nt++) {
                    mma16816(acc[mt][nt], af[mt], b0h[nt], b1h[nt]);
                    mma16816(acc[mt][nt], af[mt], b0l[nt], b1l[nt]);
                }
#pragma unroll
            for (int mt = 0; mt < 4; mt++) {
                uint32_t addr = base + O_AL +
                    (uint32_t)(((wm + mt * 16 + lrow) * GSTR + kk + lcol) * 2);
                ldsm_x4(af[mt], addr);
            }
#pragma unroll
            for (int mt = 0; mt < 4; mt++)
#pragma unroll
                for (int nt = 0; nt < 4; nt++)
                    mma16816(acc[mt][nt], af[mt], b0h[nt], b1h[nt]);
        }
        __syncthreads();
    }

#pragma unroll
    for (int mt = 0; mt < 4; mt++) {
        size_t r0 = rowA0 + wm + mt * 16 + (lane >> 2);
        size_t r1 = r0 + 8;
#pragma unroll
        for (int nt = 0; nt < 4; nt++) {
            size_t cc = rowB0 + wn + nt * 8 + (lane & 3) * 2;
            if (OUTMODE == 0) {
                *(float2*)(Cf + r0 * EMB + cc) = make_float2(acc[mt][nt][0], acc[mt][nt][1]);
                *(float2*)(Cf + r1 * EMB + cc) = make_float2(acc[mt][nt][2], acc[mt][nt][3]);
            } else {
                __nv_bfloat16 h0, l0, h1, l1;
                split1(acc[mt][nt][0], h0, l0);
                split1(acc[mt][nt][1], h1, l1);
                *(uint32_t*)(Ch + r0 * EMB + cc) = pack2(h0, h1);
                *(uint32_t*)(Cl + r0 * EMB + cc) = pack2(l0, l1);
                split1(acc[mt][nt][2], h0, l0);
                split1(acc[mt][nt][3], h1, l1);
                *(uint32_t*)(Ch + r1 * EMB + cc) = pack2(h0, h1);
                *(uint32_t*)(Cl + r1 * EMB + cc) = pack2(l0, l1);
            }
        }
    }
}

// ===========================================================================
// FA2-style flash attention: 128 q/CTA, warp = 16q x 64k, register softmax,
// P register-resident, cp.async double-buffered K/V.
// RACE FIX vs R7: trailing __syncthreads() at end of mainloop body — the
// next iteration's cp.async prefetch overwrites the stage this iteration
// reads, so all readers must arrive before the writes are issued.
// ===========================================================================
#define AQ 128
#define AK 64
#define ASTR 72
#define AROWB (ASTR * 2)       // 144 B per smem row
#define KVROWS (AK * AROWB)    // 9216 B per K/V array per stage

struct AttnSmem {
    __nv_bfloat16 Qh[AQ][ASTR], Ql[AQ][ASTR];
    __nv_bfloat16 Kh[2][AK][ASTR], Kl[2][AK][ASTR];
    __nv_bfloat16 Vh[2][AK][ASTR], Vl[2][AK][ASTR];
    unsigned char msk[2][64];
};
#define ATTN_SMEM ((int)sizeof(AttnSmem))

__global__ __launch_bounds__(256) void attn_mma(
    const __nv_bfloat16* __restrict__ Qhg, const __nv_bfloat16* __restrict__ Qlg,
    const __nv_bfloat16* __restrict__ Khg, const __nv_bfloat16* __restrict__ Klg,
    const __nv_bfloat16* __restrict__ Vhg, const __nv_bfloat16* __restrict__ Vlg,
    const unsigned char* __restrict__ mask,
    __nv_bfloat16* __restrict__ Ohg, __nv_bfloat16* __restrict__ Olg)
{
    AttnSmem& s = *reinterpret_cast<AttnSmem*>(sm_raw);
    const int b  = blockIdx.z;
    const int h  = blockIdx.y;
    const int qt = blockIdx.x;
    const int tid = threadIdx.x;
    const int wid = tid >> 5;
    const int lane = tid & 31;
    const size_t headoff = (size_t)h * HDIM;

    const uint32_t sqh = smem_u32(&s.Qh[0][0]);
    const uint32_t sql = smem_u32(&s.Ql[0][0]);
    const uint32_t skh = smem_u32(&s.Kh[0][0][0]);
    const uint32_t skl = smem_u32(&s.Kl[0][0][0]);
    const uint32_t svh = smem_u32(&s.Vh[0][0][0]);
    const uint32_t svl = smem_u32(&s.Vl[0][0][0]);
    const uint32_t smk = smem_u32(&s.msk[0][0]);

    // --- Q tile load: 128 x 64 hi/lo, 16B vector loads ---
#pragma unroll
    for (int t = 0; t < 4; t++) {
        int i = tid + t * 256;            // 0..1023
        int r = i >> 3, seg = i & 7;      // row, 16B segment
        size_t gi = ((size_t)(qt * AQ + r) * BATCH + b) * EMB + headoff + seg * 8;
        *(uint4*)((char*)&s.Qh[r][0] + seg * 16) = *(const uint4*)(Qhg + gi);
        *(uint4*)((char*)&s.Ql[r][0] + seg * 16) = *(const uint4*)(Qlg + gi);
    }

    // --- cp.async assignment: tid>>6 -> array, tid&63 -> row (8 x 16B) ---
    const int ca = tid >> 6;
    const int crow = tid & 63;
    const __nv_bfloat16* casrc = (ca == 0) ? Khg : (ca == 1) ? Klg
                                : (ca == 2) ? Vhg : Vlg;
    const uint32_t cadst = (ca == 0) ? skh : (ca == 1) ? skl
                          : (ca == 2) ? svh : svl;

    // prefetch k-tile 0 into stage 0
    {
        size_t gi = ((size_t)crow * BATCH + b) * EMB + headoff;
        const char* g = (const char*)(casrc + gi);
        uint32_t d = cadst + crow * AROWB;
#pragma unroll
        for (int seg = 0; seg < 8; seg++) cp16(d + seg * 16, g + seg * 16);
        if (tid < 4) cp16(smk + tid * 16, mask + (size_t)b * T_K + tid * 16);
    }
    CP_COMMIT();

    float m0 = -INFINITY, m1 = -INFINITY, l0 = 0.f, l1 = 0.f;
    float o[8][4];
#pragma unroll
    for (int nt = 0; nt < 8; nt++)
#pragma unroll
        for (int e = 0; e < 4; e++) o[nt][e] = 0.f;

    const uint32_t lrow = lane & 15;
    const uint32_t lcol = (lane >> 4) << 3;
    const int NT = T_K / AK;     // 32

    for (int kt = 0; kt < NT; kt++) {
        if (kt + 1 < NT) {
            int st2 = (kt + 1) & 1;
            size_t gi = ((size_t)((kt + 1) * AK + crow) * BATCH + b) * EMB + headoff;
            const char* g = (const char*)(casrc + gi);
            uint32_t d = cadst + st2 * KVROWS + crow * AROWB;
#pragma unroll
            for (int seg = 0; seg < 8; seg++) cp16(d + seg * 16, g + seg * 16);
            if (tid < 4)
                cp16(smk + st2 * 64 + tid * 16,
                     mask + (size_t)b * T_K + (kt + 1) * AK + tid * 16);
            CP_COMMIT();
            CP_WAIT(1);
        } else {
            CP_WAIT(0);
        }
        __syncthreads();

        const int st = kt & 1;
        const uint32_t kbh = skh + st * KVROWS;
        const uint32_t kbl = skl + st * KVROWS;
        const uint32_t vbh = svh + st * KVROWS;
        const uint32_t vbl = svl + st * KVROWS;
        const unsigned char* mrow = &s.msk[st][0];

        // ---- S = Q K^T (warp: 16q x 64k), 3 chains ----
        float sc[8][4];
#pragma unroll
        for (int nt = 0; nt < 8; nt++)
#pragma unroll
            for (int e = 0; e < 4; e++) sc[nt][e] = 0.f;

#pragma unroll
        for (int kk = 0; kk < 4; kk++) {
            uint32_t aoff = (uint32_t)(((wid * 16 + lrow) * ASTR + kk * 16 + lcol) * 2);
            uint32_t ah[4], al[4];
            ldsm_x4(ah, sqh + aoff);
            ldsm_x4(al, sql + aoff);
            uint32_t b0h[8], b1h[8], b0l[8], b1l[8];
#pragma unroll
            for (int g = 0; g < 4; g++) {
                uint32_t roff = (uint32_t)(((g * 16 + lrow) * ASTR + kk * 16 + lcol) * 2);
                uint32_t r4[4];
                ldsm_x4(r4, kbh + roff);
                b0h[2*g] = r4[0]; b0h[2*g+1] = r4[1];
                b1h[2*g] = r4[2]; b1h[2*g+1] = r4[3];
                ldsm_x4(r4, kbl + roff);
                b0l[2*g] = r4[0]; b0l[2*g+1] = r4[1];
                b1l[2*g] = r4[2]; b1l[2*g+1] = r4[3];
            }
#pragma unroll
            for (int nt = 0; nt < 8; nt++) {
                mma16816(sc[nt], ah, b0h[nt], b1h[nt]);
                mma16816(sc[nt], ah, b0l[nt], b1l[nt]);
                mma16816(sc[nt], al, b0h[nt], b1h[nt]);
            }
        }

        // ---- register softmax ----
        float tm0 = -INFINITY, tm1 = -INFINITY;
#pragma unroll
        for (int nt = 0; nt < 8; nt++) {
            int k0 = nt * 8 + (lane & 3) * 2;
            bool mk0 = mrow[k0] != 0, mk1 = mrow[k0 + 1] != 0;
            sc[nt][0] = mk0 ? NEGINF : sc[nt][0] * 0.125f;
            sc[nt][1] = mk1 ? NEGINF : sc[nt][1] * 0.125f;
            sc[nt][2] = mk0 ? NEGINF : sc[nt][2] * 0.125f;
            sc[nt][3] = mk1 ? NEGINF : sc[nt][3] * 0.125f;
            tm0 = fmaxf(tm0, fmaxf(sc[nt][0], sc[nt][1]));
            tm1 = fmaxf(tm1, fmaxf(sc[nt][2], sc[nt][3]));
        }
        tm0 = fmaxf(tm0, __shfl_xor_sync(0xffffffffu, tm0, 1));
        tm0 = fmaxf(tm0, __shfl_xor_sync(0xffffffffu, tm0, 2));
        tm1 = fmaxf(tm1, __shfl_xor_sync(0xffffffffu, tm1, 1));
        tm1 = fmaxf(tm1, __shfl_xor_sync(0xffffffffu, tm1, 2));

        float mn0 = fmaxf(m0, tm0), mn1 = fmaxf(m1, tm1);
        float al0 = __expf(m0 - mn0), al1 = __expf(m1 - mn1);
        m0 = mn0; m1 = mn1;

        float ts0 = 0.f, ts1 = 0.f;
        uint32_t pfh[4][4], pfl[4][4];
#pragma unroll
        for (int nt = 0; nt < 8; nt++) {
            float p0 = __expf(sc[nt][0] - mn0);
            float p1 = __expf(sc[nt][1] - mn0);
            float p2 = __expf(sc[nt][2] - mn1);
            float p3 = __expf(sc[nt][3] - mn1);
            ts0 += p0 + p1;
            ts1 += p2 + p3;
            __nv_bfloat16 h0, lo0, h1, lo1;
            int t = nt >> 1, half = (nt & 1) * 2;
            split1(p0, h0, lo0); split1(p1, h1, lo1);
            pfh[t][half + 0] = pack2(h0, h1);
            pfl[t][half + 0] = pack2(lo0, lo1);
            split1(p2, h0, lo0); split1(p3, h1, lo1);
            pfh[t][half + 1] = pack2(h0, h1);
            pfl[t][half + 1] = pack2(lo0, lo1);
        }
        ts0 += __shfl_xor_sync(0xffffffffu, ts0, 1);
        ts0 += __shfl_xor_sync(0xffffffffu, ts0, 2);
        ts1 += __shfl_xor_sync(0xffffffffu, ts1, 1);
        ts1 += __shfl_xor_sync(0xffffffffu, ts1, 2);
        l0 = l0 * al0 + ts0;
        l1 = l1 * al1 + ts1;

#pragma unroll
        for (int nt = 0; nt < 8; nt++) {
            o[nt][0] *= al0; o[nt][1] *= al0;
            o[nt][2] *= al1; o[nt][3] *= al1;
        }

        // ---- O += P V (warp: 16q x 64d), 3 chains ----
#pragma unroll
        for (int t = 0; t < 4; t++) {
            uint32_t b0h[8], b1h[8], b0l[8], b1l[8];
#pragma unroll
            for (int g = 0; g < 4; g++) {
                uint32_t vrow = (uint32_t)(t * 16 + (lane & 7) + ((lane >> 3) & 1) * 8);
                uint32_t vcol = (uint32_t)(g * 16 + ((lane >> 4) << 3));
                uint32_t roff = (vrow * ASTR + vcol) * 2;
                uint32_t r4[4];
                ldsm_x4_t(r4, vbh + roff);
                b0h[2*g] = r4[0]; b1h[2*g] = r4[1];
                b0h[2*g+1] = r4[2]; b1h[2*g+1] = r4[3];
                ldsm_x4_t(r4, vbl + roff);
                b0l[2*g] = r4[0]; b1l[2*g] = r4[1];
                b0l[2*g+1] = r4[2]; b1l[2*g+1] = r4[3];
            }
#pragma unroll
            for (int nt = 0; nt < 8; nt++) {
                mma16816(o[nt], pfh[t], b0h[nt], b1h[nt]);
                mma16816(o[nt], pfh[t], b0l[nt], b1l[nt]);
                mma16816(o[nt], pfl[t], b0h[nt], b1h[nt]);
            }
        }

        // RACE FIX: all warps must finish reading stage `st` before the next
        // iteration issues cp.async writes into it.
        __syncthreads();
    }

    // ---- finalize: /l, write bf16 hi/lo AO at (t, b, e) ----
    float inv0 = 1.f / l0;
    float inv1 = 1.f / l1;
    const int r0 = wid * 16 + (lane >> 2);
    const int r1 = r0 + 8;
    size_t tg0 = (size_t)(qt * AQ + r0) * BATCH + b;
    size_t tg1 = (size_t)(qt * AQ + r1) * BATCH + b;
#pragma unroll
    for (int nt = 0; nt < 8; nt++) {
        size_t d0 = nt * 8 + (lane & 3) * 2;
        __nv_bfloat16 h0, lo0, h1, lo1;
        split1(o[nt][0] * inv0, h0, lo0);
        split1(o[nt][1] * inv0, h1, lo1);
        *(uint32_t*)(Ohg + tg0 * EMB + headoff + d0) = pack2(h0, h1);
        *(uint32_t*)(Olg + tg0 * EMB + headoff + d0) = pack2(lo0, lo1);
        split1(o[nt][2] * inv1, h0, lo0);
        split1(o[nt][3] * inv1, h1, lo1);
        *(uint32_t*)(Ohg + tg1 * EMB + headoff + d0) = pack2(h0, h1);
        *(uint32_t*)(Olg + tg1 * EMB + headoff + d0) = pack2(lo0, lo1);
    }
}

// ===========================================================================
// Launch
// ===========================================================================
extern "C" void kernel_launch(void* const* d_in, const int* in_sizes, int n_in,
                              void* d_out, int out_size)
{
    const float* q  = (const float*)d_in[0];
    const float* k  = (const float*)d_in[1];
    const float* v  = (const float*)d_in[2];
    const void*  maskraw = d_in[3];
    const float* Wq = (const float*)d_in[4];
    const float* Wk = (const float*)d_in[5];
    const float* Wv = (const float*)d_in[6];
    const float* Wo = (const float*)d_in[7];
    float* out = (float*)d_out;

    __nv_bfloat16 *qh, *ql, *kh, *kl, *vh, *vl;
    __nv_bfloat16 *wqh, *wql, *wkh, *wkl, *wvh, *wvl, *woh, *wol;
    __nv_bfloat16 *pqh, *pql, *pkh, *pkl, *pvh, *pvl, *aoh, *aol;
    unsigned char* gmask;
    cudaGetSymbolAddress((void**)&qh, c_qh);  cudaGetSymbolAddress((void**)&ql, c_ql);
    cudaGetSymbolAddress((void**)&kh, c_kh);  cudaGetSymbolAddress((void**)&kl, c_kl);
    cudaGetSymbolAddress((void**)&vh, c_vh);  cudaGetSymbolAddress((void**)&vl, c_vl);
    cudaGetSymbolAddress((void**)&wqh, c_wqh); cudaGetSymbolAddress((void**)&wql, c_wql);
    cudaGetSymbolAddress((void**)&wkh, c_wkh); cudaGetSymbolAddress((void**)&wkl, c_wkl);
    cudaGetSymbolAddress((void**)&wvh, c_wvh); cudaGetSymbolAddress((void**)&wvl, c_wvl);
    cudaGetSymbolAddress((void**)&woh, c_woh); cudaGetSymbolAddress((void**)&wol, c_wol);
    cudaGetSymbolAddress((void**)&pqh, p_qh);  cudaGetSymbolAddress((void**)&pql, p_ql);
    cudaGetSymbolAddress((void**)&pkh, p_kh);  cudaGetSymbolAddress((void**)&pkl, p_kl);
    cudaGetSymbolAddress((void**)&pvh, p_vh);  cudaGetSymbolAddress((void**)&pvl, p_vl);
    cudaGetSymbolAddress((void**)&aoh, ao_h);  cudaGetSymbolAddress((void**)&aol, ao_l);
    cudaGetSymbolAddress((void**)&gmask, g_mask);

    cudaFuncSetAttribute(attn_mma, cudaFuncAttributeMaxDynamicSharedMemorySize,
                         ATTN_SMEM);
    cudaFuncSetAttribute(gemm_bf16<0>, cudaFuncAttributeMaxDynamicSharedMemorySize,
                         GEMM_SMEM);
    cudaFuncSetAttribute(gemm_bf16<1>, cudaFuncAttributeMaxDynamicSharedMemorySize,
                         GEMM_SMEM);

    sniff_mask_kernel<<<1, 256>>>((const unsigned char*)maskraw);
    norm_mask_kernel<<<NMASK / 256, 256>>>(maskraw);

    const int NIN = MROWS * EMB;
    const int NW  = EMB * EMB;
    conv_qkv<<<dim3(NIN / 4 / 256, 3), 256>>>(q, k, v, qh, ql, kh, kl, vh, vl);
    conv_w<<<dim3(NW / 4 / 256, 4), 256>>>(Wq, Wk, Wv, Wo,
                                           wqh, wql, wkh, wkl,
                                           wvh, wvl, woh, wol);

    dim3 ggrid(EMB / GBN, MROWS / GBM);   // (8, 64)
    gemm_bf16<1><<<ggrid, 256, GEMM_SMEM>>>(qh, ql, wqh, wql, nullptr, pqh, pql);
    gemm_bf16<1><<<ggrid, 256, GEMM_SMEM>>>(kh, kl, wkh, wkl, nullptr, pkh, pkl);
    gemm_bf16<1><<<ggrid, 256, GEMM_SMEM>>>(vh, vl, wvh, wvl, nullptr, pvh, pvl);

    dim3 agrid(T_Q / AQ, NHEADS, BATCH);  // (16, 16, 4)
    attn_mma<<<agrid, 256, ATTN_SMEM>>>(pqh, pql, pkh, pkl, pvh, pvl, gmask,
                                        aoh, aol);

    gemm_bf16<0><<<ggrid, 256, GEMM_SMEM>>>(aoh, aol, woh, wol, out,
                                            nullptr, nullptr);
}

// round 15
// speedup vs baseline: 1.1442x; 1.0451x over previous
#include <cuda_runtime.h>
#include <cuda_bf16.h>
#include <math.h>
#include <stdint.h>

#define T_Q 2048
#define T_K 2048
#define BATCH 4
#define EMB 1024
#define NHEADS 16
#define HDIM 64
#define MROWS (T_Q * BATCH)   // 8192
#define NEGINF -1e9f
#define NMASK (BATCH * T_K)   // 8192

// ---------------------------------------------------------------------------
// Static device scratch. All bf16 hi/lo pairs.
// ---------------------------------------------------------------------------
__device__ __nv_bfloat16 c_qh[MROWS * EMB], c_ql[MROWS * EMB];
__device__ __nv_bfloat16 c_kh[MROWS * EMB], c_kl[MROWS * EMB];
__device__ __nv_bfloat16 c_vh[MROWS * EMB], c_vl[MROWS * EMB];
__device__ __nv_bfloat16 c_wqh[EMB * EMB], c_wql[EMB * EMB];
__device__ __nv_bfloat16 c_wkh[EMB * EMB], c_wkl[EMB * EMB];
__device__ __nv_bfloat16 c_wvh[EMB * EMB], c_wvl[EMB * EMB];
__device__ __nv_bfloat16 c_woh[EMB * EMB], c_wol[EMB * EMB];
__device__ __nv_bfloat16 p_qh[MROWS * EMB], p_ql[MROWS * EMB];
__device__ __nv_bfloat16 p_kh[MROWS * EMB], p_kl[MROWS * EMB];
__device__ __nv_bfloat16 p_vh[MROWS * EMB], p_vl[MROWS * EMB];
__device__ __nv_bfloat16 ao_h[MROWS * EMB], ao_l[MROWS * EMB];
__device__ __align__(16) unsigned char g_mask[NMASK];
__device__ int g_mask_kind;

// ===========================================================================
// helpers
// ===========================================================================
__device__ __forceinline__ uint32_t smem_u32(const void* p) {
    uint32_t a;
    asm("{ .reg .u64 t; cvta.to.shared.u64 t, %1; cvt.u32.u64 %0, t; }"
        : "=r"(a) : "l"(p));
    return a;
}
__device__ __forceinline__ void mma16816(float* c, const uint32_t* a,
                                         uint32_t b0, uint32_t b1) {
    asm volatile(
        "mma.sync.aligned.m16n8k16.row.col.f32.bf16.bf16.f32 "
        "{%0,%1,%2,%3}, {%4,%5,%6,%7}, {%8,%9}, {%0,%1,%2,%3};"
        : "+f"(c[0]), "+f"(c[1]), "+f"(c[2]), "+f"(c[3])
        : "r"(a[0]), "r"(a[1]), "r"(a[2]), "r"(a[3]), "r"(b0), "r"(b1));
}
__device__ __forceinline__ void ldsm_x4(uint32_t* r, uint32_t addr) {
    asm volatile("ldmatrix.sync.aligned.m8n8.x4.shared.b16 {%0,%1,%2,%3}, [%4];"
        : "=r"(r[0]), "=r"(r[1]), "=r"(r[2]), "=r"(r[3]) : "r"(addr));
}
__device__ __forceinline__ void ldsm_x4_t(uint32_t* r, uint32_t addr) {
    asm volatile("ldmatrix.sync.aligned.m8n8.x4.trans.shared.b16 {%0,%1,%2,%3}, [%4];"
        : "=r"(r[0]), "=r"(r[1]), "=r"(r[2]), "=r"(r[3]) : "r"(addr));
}
__device__ __forceinline__ void cp16(uint32_t sm, const void* g) {
    asm volatile("cp.async.cg.shared.global [%0], [%1], 16;" :: "r"(sm), "l"(g));
}
#define CP_COMMIT() asm volatile("cp.async.commit_group;" ::: "memory")
#define CP_WAIT(n)  asm volatile("cp.async.wait_group %0;" :: "n"(n) : "memory")

__device__ __forceinline__ void split1(float x, __nv_bfloat16& h, __nv_bfloat16& l) {
    h = __float2bfloat16(x);
    l = __float2bfloat16(x - __bfloat162float(h));
}
__device__ __forceinline__ uint32_t pack2(__nv_bfloat16 a, __nv_bfloat16 b) {
    return (uint32_t)__bfloat16_as_ushort(a) | ((uint32_t)__bfloat16_as_ushort(b) << 16);
}
__device__ __forceinline__ void split4(float4 v, uint2& hw, uint2& lw) {
    __nv_bfloat16 h0, h1, h2, h3, l0, l1, l2, l3;
    split1(v.x, h0, l0); split1(v.y, h1, l1);
    split1(v.z, h2, l2); split1(v.w, h3, l3);
    hw.x = pack2(h0, h1); hw.y = pack2(h2, h3);
    lw.x = pack2(l0, l1); lw.y = pack2(l2, l3);
}

// ===========================================================================
// batched fp32 -> bf16 hi/lo converters (R13-proven)
// ===========================================================================
__global__ void conv_qkv(const float* __restrict__ q, const float* __restrict__ k,
                         const float* __restrict__ v,
                         __nv_bfloat16* __restrict__ qh, __nv_bfloat16* __restrict__ ql,
                         __nv_bfloat16* __restrict__ kh, __nv_bfloat16* __restrict__ kl,
                         __nv_bfloat16* __restrict__ vh, __nv_bfloat16* __restrict__ vl)
{
    const float* x = (blockIdx.y == 0) ? q : (blockIdx.y == 1) ? k : v;
    __nv_bfloat16* h = (blockIdx.y == 0) ? qh : (blockIdx.y == 1) ? kh : vh;
    __nv_bfloat16* l = (blockIdx.y == 0) ? ql : (blockIdx.y == 1) ? kl : vl;
    int i = (blockIdx.x * blockDim.x + threadIdx.x) * 4;
    float4 vv = *(const float4*)(x + i);
    uint2 hw, lw;
    split4(vv, hw, lw);
    *(uint2*)(h + i) = hw;
    *(uint2*)(l + i) = lw;
}

__global__ void conv_w(const float* __restrict__ w0, const float* __restrict__ w1,
                       const float* __restrict__ w2, const float* __restrict__ w3,
                       __nv_bfloat16* __restrict__ h0, __nv_bfloat16* __restrict__ l0,
                       __nv_bfloat16* __restrict__ h1, __nv_bfloat16* __restrict__ l1,
                       __nv_bfloat16* __restrict__ h2, __nv_bfloat16* __restrict__ l2,
                       __nv_bfloat16* __restrict__ h3, __nv_bfloat16* __restrict__ l3)
{
    int wsel = blockIdx.y;
    const float* x = (wsel == 0) ? w0 : (wsel == 1) ? w1 : (wsel == 2) ? w2 : w3;
    __nv_bfloat16* h = (wsel == 0) ? h0 : (wsel == 1) ? h1 : (wsel == 2) ? h2 : h3;
    __nv_bfloat16* l = (wsel == 0) ? l0 : (wsel == 1) ? l1 : (wsel == 2) ? l2 : l3;
    int i = (blockIdx.x * blockDim.x + threadIdx.x) * 4;
    float4 vv = *(const float4*)(x + i);
    uint2 hw, lw;
    split4(vv, hw, lw);
    *(uint2*)(h + i) = hw;
    *(uint2*)(l + i) = lw;
}

// ===========================================================================
// Mask dtype sniff + normalization (verified R3)
// ===========================================================================
__global__ void sniff_mask_kernel(const unsigned char* __restrict__ m)
{
    __shared__ int nz_off, nz_al;
    if (threadIdx.x == 0) { nz_off = 0; nz_al = 0; }
    __syncthreads();
    int loc_off = 0, loc_al = 0;
    for (int i = threadIdx.x; i < NMASK; i += blockDim.x) {
        unsigned char v = m[i];
        if (v) { if (i & 3) loc_off = 1; else loc_al = 1; }
    }
    if (loc_off) atomicOr(&nz_off, 1);
    if (loc_al)  atomicOr(&nz_al, 1);
    __syncthreads();
    if (threadIdx.x == 0) {
        int kind;
        if (!nz_off)     kind = 1;
        else if (!nz_al) kind = 2;
        else             kind = 0;
        g_mask_kind = kind;
    }
}

__global__ void norm_mask_kernel(const void* __restrict__ m)
{
    int i = blockIdx.x * blockDim.x + threadIdx.x;
    if (i >= NMASK) return;
    int kind = g_mask_kind;
    unsigned char r;
    if (kind == 1)      r = (((const int*)m)[i]   != 0);
    else if (kind == 2) r = (((const float*)m)[i] != 0.f);
    else                r = (((const unsigned char*)m)[i] != 0);
    g_mask[i] = r;
}

// ===========================================================================
// HMMA GEMM NT core (R13-proven body): C = A*B^T, bf16 hi/lo x3 chains,
// cp.async 2-stage (issue -> commit -> wait(1) -> sync -> compute -> sync).
// ===========================================================================
#define GBM 128
#define GBN 128
#define GBK 32
#define GSTR 40
#define ARR_SZ (128 * GSTR * 2)
#define STAGE_SZ (4 * ARR_SZ)
#define GEMM_SMEM (2 * STAGE_SZ)
#define O_AH 0
#define O_AL ARR_SZ
#define O_BH (2 * ARR_SZ)
#define O_BL (3 * ARR_SZ)

extern __shared__ char sm_raw[];

template <int OUTMODE>
__device__ __forceinline__ void gemm_core(
    const __nv_bfloat16* __restrict__ Agh, const __nv_bfloat16* __restrict__ Agl,
    const __nv_bfloat16* __restrict__ Bgh, const __nv_bfloat16* __restrict__ Bgl,
    float* __restrict__ Cf,
    __nv_bfloat16* __restrict__ Ch, __nv_bfloat16* __restrict__ Cl)
{
    uint32_t sb = smem_u32(sm_raw);
    const int tid = threadIdx.x;
    const int wid = tid >> 5;
    const int lane = tid & 31;
    const int wm = (wid & 1) * 64;
    const int wn = (wid >> 1) * 32;
    const size_t rowA0 = (size_t)blockIdx.y * GBM;
    const size_t rowB0 = (size_t)blockIdx.x * GBN;

    const int carr = tid >> 6;
    const int crow0 = (tid & 63) >> 1;
    const int cseg = (tid & 1) << 1;
    const __nv_bfloat16* gbase[4] = {
        Agh + rowA0 * EMB, Agl + rowA0 * EMB,
        Bgh + rowB0 * EMB, Bgl + rowB0 * EMB };
    const __nv_bfloat16* mygb = gbase[carr];
    const uint32_t myarr = sb + carr * ARR_SZ;

    float acc[4][4][4];
#pragma unroll
    for (int mt = 0; mt < 4; mt++)
#pragma unroll
        for (int nt = 0; nt < 4; nt++)
#pragma unroll
            for (int e = 0; e < 4; e++) acc[mt][nt][e] = 0.f;

    const int NCH = EMB / GBK;   // 32

#pragma unroll
    for (int rr = 0; rr < 4; rr++) {
        int row = crow0 + rr * 32;
        uint32_t smaddr = myarr + row * (GSTR * 2) + cseg * 16;
        const void* g = mygb + (size_t)row * EMB + cseg * 8;
        cp16(smaddr, g);
        cp16(smaddr + 16, (const char*)g + 16);
    }
    CP_COMMIT();

    for (int c = 0; c < NCH; c++) {
        if (c + 1 < NCH) {
            const int kt = (c + 1) * GBK;
            const uint32_t stb = myarr + ((c + 1) & 1) * STAGE_SZ;
#pragma unroll
            for (int rr = 0; rr < 4; rr++) {
                int row = crow0 + rr * 32;
                uint32_t smaddr = stb + row * (GSTR * 2) + cseg * 16;
                const void* g = mygb + (size_t)row * EMB + kt + cseg * 8;
                cp16(smaddr, g);
                cp16(smaddr + 16, (const char*)g + 16);
            }
            CP_COMMIT();
            CP_WAIT(1);
        } else {
            CP_WAIT(0);
        }
        __syncthreads();

        const uint32_t base = sb + (uint32_t)(c & 1) * STAGE_SZ;
        const uint32_t lrow = lane & 15;
        const uint32_t lcol = (lane >> 4) << 3;
#pragma unroll
        for (int kk = 0; kk < GBK; kk += 16) {
            uint32_t af[4][4];
#pragma unroll
            for (int mt = 0; mt < 4; mt++) {
                uint32_t addr = base + O_AH +
                    (uint32_t)(((wm + mt * 16 + lrow) * GSTR + kk + lcol) * 2);
                ldsm_x4(af[mt], addr);
            }
            uint32_t b0h[4], b1h[4], b0l[4], b1l[4];
#pragma unroll
            for (int g = 0; g < 2; g++) {
                uint32_t roff = (uint32_t)(((wn + g * 16 + lrow) * GSTR + kk + lcol) * 2);
                uint32_t r4[4];
                ldsm_x4(r4, base + O_BH + roff);
                b0h[2 * g] = r4[0]; b0h[2 * g + 1] = r4[1];
                b1h[2 * g] = r4[2]; b1h[2 * g + 1] = r4[3];
                ldsm_x4(r4, base + O_BL + roff);
                b0l[2 * g] = r4[0]; b0l[2 * g + 1] = r4[1];
                b1l[2 * g] = r4[2]; b1l[2 * g + 1] = r4[3];
            }
#pragma unroll
            for (int mt = 0; mt < 4; mt++)
#pragma unroll
                for (int nt = 0; nt < 4; nt++) {
                    mma16816(acc[mt][nt], af[mt], b0h[nt], b1h[nt]);
                    mma16816(acc[mt][nt], af[mt], b0l[nt], b1l[nt]);
                }
#pragma unroll
            for (int mt = 0; mt < 4; mt++) {
                uint32_t addr = base + O_AL +
                    (uint32_t)(((wm + mt * 16 + lrow) * GSTR + kk + lcol) * 2);
                ldsm_x4(af[mt], addr);
            }
#pragma unroll
            for (int mt = 0; mt < 4; mt++)
#pragma unroll
                for (int nt = 0; nt < 4; nt++)
                    mma16816(acc[mt][nt], af[mt], b0h[nt], b1h[nt]);
        }
        __syncthreads();
    }

#pragma unroll
    for (int mt = 0; mt < 4; mt++) {
        size_t r0 = rowA0 + wm + mt * 16 + (lane >> 2);
        size_t r1 = r0 + 8;
#pragma unroll
        for (int nt = 0; nt < 4; nt++) {
            size_t cc = rowB0 + wn + nt * 8 + (lane & 3) * 2;
            if (OUTMODE == 0) {
                *(float2*)(Cf + r0 * EMB + cc) = make_float2(acc[mt][nt][0], acc[mt][nt][1]);
                *(float2*)(Cf + r1 * EMB + cc) = make_float2(acc[mt][nt][2], acc[mt][nt][3]);
            } else {
                __nv_bfloat16 h0, l0, h1, l1;
                split1(acc[mt][nt][0], h0, l0);
                split1(acc[mt][nt][1], h1, l1);
                *(uint32_t*)(Ch + r0 * EMB + cc) = pack2(h0, h1);
                *(uint32_t*)(Cl + r0 * EMB + cc) = pack2(l0, l1);
                split1(acc[mt][nt][2], h0, l0);
                split1(acc[mt][nt][3], h1, l1);
                *(uint32_t*)(Ch + r1 * EMB + cc) = pack2(h0, h1);
                *(uint32_t*)(Cl + r1 * EMB + cc) = pack2(l0, l1);
            }
        }
    }
}

// Merged Q/K/V projection launch: blockIdx.z selects the problem.
__global__ __launch_bounds__(256, 2) void gemm_qkv(
    const __nv_bfloat16* qh, const __nv_bfloat16* ql,
    const __nv_bfloat16* kh, const __nv_bfloat16* kl,
    const __nv_bfloat16* vh, const __nv_bfloat16* vl,
    const __nv_bfloat16* wqh, const __nv_bfloat16* wql,
    const __nv_bfloat16* wkh, const __nv_bfloat16* wkl,
    const __nv_bfloat16* wvh, const __nv_bfloat16* wvl,
    __nv_bfloat16* pqh, __nv_bfloat16* pql,
    __nv_bfloat16* pkh, __nv_bfloat16* pkl,
    __nv_bfloat16* pvh, __nv_bfloat16* pvl)
{
    const int z = blockIdx.z;
    const __nv_bfloat16* Agh = (z == 0) ? qh : (z == 1) ? kh : vh;
    const __nv_bfloat16* Agl = (z == 0) ? ql : (z == 1) ? kl : vl;
    const __nv_bfloat16* Bgh = (z == 0) ? wqh : (z == 1) ? wkh : wvh;
    const __nv_bfloat16* Bgl = (z == 0) ? wql : (z == 1) ? wkl : wvl;
    __nv_bfloat16* Ch = (z == 0) ? pqh : (z == 1) ? pkh : pvh;
    __nv_bfloat16* Cl = (z == 0) ? pql : (z == 1) ? pkl : pvl;
    gemm_core<1>(Agh, Agl, Bgh, Bgl, nullptr, Ch, Cl);
}

__global__ __launch_bounds__(256, 2) void gemm_out(
    const __nv_bfloat16* Agh, const __nv_bfloat16* Agl,
    const __nv_bfloat16* Bgh, const __nv_bfloat16* Bgl,
    float* Cf)
{
    gemm_core<0>(Agh, Agl, Bgh, Bgl, Cf, nullptr, nullptr);
}

// ===========================================================================
// FA2-style flash attention (R13-proven, race-free): 128 q/CTA,
// warp = 16q x 64k, register softmax, P register-resident,
// cp.async double-buffered K/V with trailing barrier.
// ===========================================================================
#define AQ 128
#define AK 64
#define ASTR 72
#define AROWB (ASTR * 2)       // 144 B per smem row
#define KVROWS (AK * AROWB)    // 9216 B per K/V array per stage

struct AttnSmem {
    __nv_bfloat16 Qh[AQ][ASTR], Ql[AQ][ASTR];
    __nv_bfloat16 Kh[2][AK][ASTR], Kl[2][AK][ASTR];
    __nv_bfloat16 Vh[2][AK][ASTR], Vl[2][AK][ASTR];
    unsigned char msk[2][64];
};
#define ATTN_SMEM ((int)sizeof(AttnSmem))

__global__ __launch_bounds__(256) void attn_mma(
    const __nv_bfloat16* __restrict__ Qhg, const __nv_bfloat16* __restrict__ Qlg,
    const __nv_bfloat16* __restrict__ Khg, const __nv_bfloat16* __restrict__ Klg,
    const __nv_bfloat16* __restrict__ Vhg, const __nv_bfloat16* __restrict__ Vlg,
    const unsigned char* __restrict__ mask,
    __nv_bfloat16* __restrict__ Ohg, __nv_bfloat16* __restrict__ Olg)
{
    AttnSmem& s = *reinterpret_cast<AttnSmem*>(sm_raw);
    const int b  = blockIdx.z;
    const int h  = blockIdx.y;
    const int qt = blockIdx.x;
    const int tid = threadIdx.x;
    const int wid = tid >> 5;
    const int lane = tid & 31;
    const size_t headoff = (size_t)h * HDIM;

    const uint32_t sqh = smem_u32(&s.Qh[0][0]);
    const uint32_t sql = smem_u32(&s.Ql[0][0]);
    const uint32_t skh = smem_u32(&s.Kh[0][0][0]);
    const uint32_t skl = smem_u32(&s.Kl[0][0][0]);
    const uint32_t svh = smem_u32(&s.Vh[0][0][0]);
    const uint32_t svl = smem_u32(&s.Vl[0][0][0]);
    const uint32_t smk = smem_u32(&s.msk[0][0]);

    // --- Q tile load: 128 x 64 hi/lo, 16B vector loads ---
#pragma unroll
    for (int t = 0; t < 4; t++) {
        int i = tid + t * 256;            // 0..1023
        int r = i >> 3, seg = i & 7;      // row, 16B segment
        size_t gi = ((size_t)(qt * AQ + r) * BATCH + b) * EMB + headoff + seg * 8;
        *(uint4*)((char*)&s.Qh[r][0] + seg * 16) = *(const uint4*)(Qhg + gi);
        *(uint4*)((char*)&s.Ql[r][0] + seg * 16) = *(const uint4*)(Qlg + gi);
    }

    // --- cp.async assignment: tid>>6 -> array, tid&63 -> row (8 x 16B) ---
    const int ca = tid >> 6;
    const int crow = tid & 63;
    const __nv_bfloat16* casrc = (ca == 0) ? Khg : (ca == 1) ? Klg
                                : (ca == 2) ? Vhg : Vlg;
    const uint32_t cadst = (ca == 0) ? skh : (ca == 1) ? skl
                          : (ca == 2) ? svh : svl;

    // prefetch k-tile 0 into stage 0
    {
        size_t gi = ((size_t)crow * BATCH + b) * EMB + headoff;
        const char* g = (const char*)(casrc + gi);
        uint32_t d = cadst + crow * AROWB;
#pragma unroll
        for (int seg = 0; seg < 8; seg++) cp16(d + seg * 16, g + seg * 16);
        if (tid < 4) cp16(smk + tid * 16, mask + (size_t)b * T_K + tid * 16);
    }
    CP_COMMIT();

    float m0 = -INFINITY, m1 = -INFINITY, l0 = 0.f, l1 = 0.f;
    float o[8][4];
#pragma unroll
    for (int nt = 0; nt < 8; nt++)
#pragma unroll
        for (int e = 0; e < 4; e++) o[nt][e] = 0.f;

    const uint32_t lrow = lane & 15;
    const uint32_t lcol = (lane >> 4) << 3;
    const int NT = T_K / AK;     // 32

    for (int kt = 0; kt < NT; kt++) {
        if (kt + 1 < NT) {
            int st2 = (kt + 1) & 1;
            size_t gi = ((size_t)((kt + 1) * AK + crow) * BATCH + b) * EMB + headoff;
            const char* g = (const char*)(casrc + gi);
            uint32_t d = cadst + st2 * KVROWS + crow * AROWB;
#pragma unroll
            for (int seg = 0; seg < 8; seg++) cp16(d + seg * 16, g + seg * 16);
            if (tid < 4)
                cp16(smk + st2 * 64 + tid * 16,
                     mask + (size_t)b * T_K + (kt + 1) * AK + tid * 16);
            CP_COMMIT();
            CP_WAIT(1);
        } else {
            CP_WAIT(0);
        }
        __syncthreads();

        const int st = kt & 1;
        const uint32_t kbh = skh + st * KVROWS;
        const uint32_t kbl = skl + st * KVROWS;
        const uint32_t vbh = svh + st * KVROWS;
        const uint32_t vbl = svl + st * KVROWS;
        const unsigned char* mrow = &s.msk[st][0];

        // ---- S = Q K^T (warp: 16q x 64k), 3 chains ----
        float sc[8][4];
#pragma unroll
        for (int nt = 0; nt < 8; nt++)
#pragma unroll
            for (int e = 0; e < 4; e++) sc[nt][e] = 0.f;

#pragma unroll
        for (int kk = 0; kk < 4; kk++) {
            uint32_t aoff = (uint32_t)(((wid * 16 + lrow) * ASTR + kk * 16 + lcol) * 2);
            uint32_t ah[4], al[4];
            ldsm_x4(ah, sqh + aoff);
            ldsm_x4(al, sql + aoff);
            uint32_t b0h[8], b1h[8], b0l[8], b1l[8];
#pragma unroll
            for (int g = 0; g < 4; g++) {
                uint32_t roff = (uint32_t)(((g * 16 + lrow) * ASTR + kk * 16 + lcol) * 2);
                uint32_t r4[4];
                ldsm_x4(r4, kbh + roff);
                b0h[2*g] = r4[0]; b0h[2*g+1] = r4[1];
                b1h[2*g] = r4[2]; b1h[2*g+1] = r4[3];
                ldsm_x4(r4, kbl + roff);
                b0l[2*g] = r4[0]; b0l[2*g+1] = r4[1];
                b1l[2*g] = r4[2]; b1l[2*g+1] = r4[3];
            }
#pragma unroll
            for (int nt = 0; nt < 8; nt++) {
                mma16816(sc[nt], ah, b0h[nt], b1h[nt]);
                mma16816(sc[nt], ah, b0l[nt], b1l[nt]);
                mma16816(sc[nt], al, b0h[nt], b1h[nt]);
            }
        }

        // ---- register softmax ----
        float tm0 = -INFINITY, tm1 = -INFINITY;
#pragma unroll
        for (int nt = 0; nt < 8; nt++) {
            int k0 = nt * 8 + (lane & 3) * 2;
            bool mk0 = mrow[k0] != 0, mk1 = mrow[k0 + 1] != 0;
            sc[nt][0] = mk0 ? NEGINF : sc[nt][0] * 0.125f;
            sc[nt][1] = mk1 ? NEGINF : sc[nt][1] * 0.125f;
            sc[nt][2] = mk0 ? NEGINF : sc[nt][2] * 0.125f;
            sc[nt][3] = mk1 ? NEGINF : sc[nt][3] * 0.125f;
            tm0 = fmaxf(tm0, fmaxf(sc[nt][0], sc[nt][1]));
            tm1 = fmaxf(tm1, fmaxf(sc[nt][2], sc[nt][3]));
        }
        tm0 = fmaxf(tm0, __shfl_xor_sync(0xffffffffu, tm0, 1));
        tm0 = fmaxf(tm0, __shfl_xor_sync(0xffffffffu, tm0, 2));
        tm1 = fmaxf(tm1, __shfl_xor_sync(0xffffffffu, tm1, 1));
        tm1 = fmaxf(tm1, __shfl_xor_sync(0xffffffffu, tm1, 2));

        float mn0 = fmaxf(m0, tm0), mn1 = fmaxf(m1, tm1);
        float al0 = __expf(m0 - mn0), al1 = __expf(m1 - mn1);
        m0 = mn0; m1 = mn1;

        float ts0 = 0.f, ts1 = 0.f;
        uint32_t pfh[4][4], pfl[4][4];
#pragma unroll
        for (int nt = 0; nt < 8; nt++) {
            float p0 = __expf(sc[nt][0] - mn0);
            float p1 = __expf(sc[nt][1] - mn0);
            float p2 = __expf(sc[nt][2] - mn1);
            float p3 = __expf(sc[nt][3] - mn1);
            ts0 += p0 + p1;
            ts1 += p2 + p3;
            __nv_bfloat16 h0, lo0, h1, lo1;
            int t = nt >> 1, half = (nt & 1) * 2;
            split1(p0, h0, lo0); split1(p1, h1, lo1);
            pfh[t][half + 0] = pack2(h0, h1);
            pfl[t][half + 0] = pack2(lo0, lo1);
            split1(p2, h0, lo0); split1(p3, h1, lo1);
            pfh[t][half + 1] = pack2(h0, h1);
            pfl[t][half + 1] = pack2(lo0, lo1);
        }
        ts0 += __shfl_xor_sync(0xffffffffu, ts0, 1);
        ts0 += __shfl_xor_sync(0xffffffffu, ts0, 2);
        ts1 += __shfl_xor_sync(0xffffffffu, ts1, 1);
        ts1 += __shfl_xor_sync(0xffffffffu, ts1, 2);
        l0 = l0 * al0 + ts0;
        l1 = l1 * al1 + ts1;

#pragma unroll
        for (int nt = 0; nt < 8; nt++) {
            o[nt][0] *= al0; o[nt][1] *= al0;
            o[nt][2] *= al1; o[nt][3] *= al1;
        }

        // ---- O += P V (warp: 16q x 64d), 3 chains ----
#pragma unroll
        for (int t = 0; t < 4; t++) {
            uint32_t b0h[8], b1h[8], b0l[8], b1l[8];
#pragma unroll
            for (int g = 0; g < 4; g++) {
                uint32_t vrow = (uint32_t)(t * 16 + (lane & 7) + ((lane >> 3) & 1) * 8);
                uint32_t vcol = (uint32_t)(g * 16 + ((lane >> 4) << 3));
                uint32_t roff = (vrow * ASTR + vcol) * 2;
                uint32_t r4[4];
                ldsm_x4_t(r4, vbh + roff);
                b0h[2*g] = r4[0]; b1h[2*g] = r4[1];
                b0h[2*g+1] = r4[2]; b1h[2*g+1] = r4[3];
                ldsm_x4_t(r4, vbl + roff);
                b0l[2*g] = r4[0]; b1l[2*g] = r4[1];
                b0l[2*g+1] = r4[2]; b1l[2*g+1] = r4[3];
            }
#pragma unroll
            for (int nt = 0; nt < 8; nt++) {
                mma16816(o[nt], pfh[t], b0h[nt], b1h[nt]);
                mma16816(o[nt], pfh[t], b0l[nt], b1l[nt]);
                mma16816(o[nt], pfl[t], b0h[nt], b1h[nt]);
            }
        }

        // RACE FIX: all warps must finish reading stage `st` before the next
        // iteration issues cp.async writes into it.
        __syncthreads();
    }

    // ---- finalize: /l, write bf16 hi/lo AO at (t, b, e) ----
    float inv0 = 1.f / l0;
    float inv1 = 1.f / l1;
    const int r0 = wid * 16 + (lane >> 2);
    const int r1 = r0 + 8;
    size_t tg0 = (size_t)(qt * AQ + r0) * BATCH + b;
    size_t tg1 = (size_t)(qt * AQ + r1) * BATCH + b;
#pragma unroll
    for (int nt = 0; nt < 8; nt++) {
        size_t d0 = nt * 8 + (lane & 3) * 2;
        __nv_bfloat16 h0, lo0, h1, lo1;
        split1(o[nt][0] * inv0, h0, lo0);
        split1(o[nt][1] * inv0, h1, lo1);
        *(uint32_t*)(Ohg + tg0 * EMB + headoff + d0) = pack2(h0, h1);
        *(uint32_t*)(Olg + tg0 * EMB + headoff + d0) = pack2(lo0, lo1);
        split1(o[nt][2] * inv1, h0, lo0);
        split1(o[nt][3] * inv1, h1, lo1);
        *(uint32_t*)(Ohg + tg1 * EMB + headoff + d0) = pack2(h0, h1);
        *(uint32_t*)(Olg + tg1 * EMB + headoff + d0) = pack2(lo0, lo1);
    }
}

// ===========================================================================
// Launch
// ===========================================================================
extern "C" void kernel_launch(void* const* d_in, const int* in_sizes, int n_in,
                              void* d_out, int out_size)
{
    const float* q  = (const float*)d_in[0];
    const float* k  = (const float*)d_in[1];
    const float* v  = (const float*)d_in[2];
    const void*  maskraw = d_in[3];
    const float* Wq = (const float*)d_in[4];
    const float* Wk = (const float*)d_in[5];
    const float* Wv = (const float*)d_in[6];
    const float* Wo = (const float*)d_in[7];
    float* out = (float*)d_out;

    __nv_bfloat16 *qh, *ql, *kh, *kl, *vh, *vl;
    __nv_bfloat16 *wqh, *wql, *wkh, *wkl, *wvh, *wvl, *woh, *wol;
    __nv_bfloat16 *pqh, *pql, *pkh, *pkl, *pvh, *pvl, *aoh, *aol;
    unsigned char* gmask;
    cudaGetSymbolAddress((void**)&qh, c_qh);  cudaGetSymbolAddress((void**)&ql, c_ql);
    cudaGetSymbolAddress((void**)&kh, c_kh);  cudaGetSymbolAddress((void**)&kl, c_kl);
    cudaGetSymbolAddress((void**)&vh, c_vh);  cudaGetSymbolAddress((void**)&vl, c_vl);
    cudaGetSymbolAddress((void**)&wqh, c_wqh); cudaGetSymbolAddress((void**)&wql, c_wql);
    cudaGetSymbolAddress((void**)&wkh, c_wkh); cudaGetSymbolAddress((void**)&wkl, c_wkl);
    cudaGetSymbolAddress((void**)&wvh, c_wvh); cudaGetSymbolAddress((void**)&wvl, c_wvl);
    cudaGetSymbolAddress((void**)&woh, c_woh); cudaGetSymbolAddress((void**)&wol, c_wol);
    cudaGetSymbolAddress((void**)&pqh, p_qh);  cudaGetSymbolAddress((void**)&pql, p_ql);
    cudaGetSymbolAddress((void**)&pkh, p_kh);  cudaGetSymbolAddress((void**)&pkl, p_kl);
    cudaGetSymbolAddress((void**)&pvh, p_vh);  cudaGetSymbolAddress((void**)&pvl, p_vl);
    cudaGetSymbolAddress((void**)&aoh, ao_h);  cudaGetSymbolAddress((void**)&aol, ao_l);
    cudaGetSymbolAddress((void**)&gmask, g_mask);

    cudaFuncSetAttribute(attn_mma, cudaFuncAttributeMaxDynamicSharedMemorySize,
                         ATTN_SMEM);
    cudaFuncSetAttribute(gemm_qkv, cudaFuncAttributeMaxDynamicSharedMemorySize,
                         GEMM_SMEM);
    cudaFuncSetAttribute(gemm_out, cudaFuncAttributeMaxDynamicSharedMemorySize,
                         GEMM_SMEM);

    sniff_mask_kernel<<<1, 256>>>((const unsigned char*)maskraw);
    norm_mask_kernel<<<NMASK / 256, 256>>>(maskraw);

    const int NIN = MROWS * EMB;
    const int NW  = EMB * EMB;
    conv_qkv<<<dim3(NIN / 4 / 256, 3), 256>>>(q, k, v, qh, ql, kh, kl, vh, vl);
    conv_w<<<dim3(NW / 4 / 256, 4), 256>>>(Wq, Wk, Wv, Wo,
                                           wqh, wql, wkh, wkl,
                                           wvh, wvl, woh, wol);

    dim3 ggrid3(EMB / GBN, MROWS / GBM, 3);   // (8, 64, 3)
    gemm_qkv<<<ggrid3, 256, GEMM_SMEM>>>(qh, ql, kh, kl, vh, vl,
                                         wqh, wql, wkh, wkl, wvh, wvl,
                                         pqh, pql, pkh, pkl, pvh, pvl);

    dim3 agrid(T_Q / AQ, NHEADS, BATCH);  // (16, 16, 4)
    attn_mma<<<agrid, 256, ATTN_SMEM>>>(pqh, pql, pkh, pkl, pvh, pvl, gmask,
                                        aoh, aol);

    dim3 ggrid(EMB / GBN, MROWS / GBM);   // (8, 64)
    gemm_out<<<ggrid, 256, GEMM_SMEM>>>(aoh, aol, woh, wol, out);
}

// round 16
// speedup vs baseline: 1.1458x; 1.0014x over previous
#include <cuda_runtime.h>
#include <cuda_bf16.h>
#include <math.h>
#include <stdint.h>

#define T_Q 2048
#define T_K 2048
#define BATCH 4
#define EMB 1024
#define NHEADS 16
#define HDIM 64
#define MROWS (T_Q * BATCH)   // 8192
#define NEGINF -1e9f
#define NMASK (BATCH * T_K)   // 8192

// ---------------------------------------------------------------------------
// Static device scratch. All bf16 hi/lo pairs.
// ---------------------------------------------------------------------------
__device__ __nv_bfloat16 c_qh[MROWS * EMB], c_ql[MROWS * EMB];
__device__ __nv_bfloat16 c_kh[MROWS * EMB], c_kl[MROWS * EMB];
__device__ __nv_bfloat16 c_vh[MROWS * EMB], c_vl[MROWS * EMB];
__device__ __nv_bfloat16 c_wqh[EMB * EMB], c_wql[EMB * EMB];
__device__ __nv_bfloat16 c_wkh[EMB * EMB], c_wkl[EMB * EMB];
__device__ __nv_bfloat16 c_wvh[EMB * EMB], c_wvl[EMB * EMB];
__device__ __nv_bfloat16 c_woh[EMB * EMB], c_wol[EMB * EMB];
__device__ __nv_bfloat16 p_qh[MROWS * EMB], p_ql[MROWS * EMB];
__device__ __nv_bfloat16 p_kh[MROWS * EMB], p_kl[MROWS * EMB];
__device__ __nv_bfloat16 p_vh[MROWS * EMB], p_vl[MROWS * EMB];
__device__ __nv_bfloat16 ao_h[MROWS * EMB], ao_l[MROWS * EMB];
__device__ __align__(16) unsigned char g_mask[NMASK];

// ===========================================================================
// helpers
// ===========================================================================
__device__ __forceinline__ uint32_t smem_u32(const void* p) {
    uint32_t a;
    asm("{ .reg .u64 t; cvta.to.shared.u64 t, %1; cvt.u32.u64 %0, t; }"
        : "=r"(a) : "l"(p));
    return a;
}
__device__ __forceinline__ void mma16816(float* c, const uint32_t* a,
                                         uint32_t b0, uint32_t b1) {
    asm volatile(
        "mma.sync.aligned.m16n8k16.row.col.f32.bf16.bf16.f32 "
        "{%0,%1,%2,%3}, {%4,%5,%6,%7}, {%8,%9}, {%0,%1,%2,%3};"
        : "+f"(c[0]), "+f"(c[1]), "+f"(c[2]), "+f"(c[3])
        : "r"(a[0]), "r"(a[1]), "r"(a[2]), "r"(a[3]), "r"(b0), "r"(b1));
}
__device__ __forceinline__ void ldsm_x4(uint32_t* r, uint32_t addr) {
    asm volatile("ldmatrix.sync.aligned.m8n8.x4.shared.b16 {%0,%1,%2,%3}, [%4];"
        : "=r"(r[0]), "=r"(r[1]), "=r"(r[2]), "=r"(r[3]) : "r"(addr));
}
__device__ __forceinline__ void ldsm_x4_t(uint32_t* r, uint32_t addr) {
    asm volatile("ldmatrix.sync.aligned.m8n8.x4.trans.shared.b16 {%0,%1,%2,%3}, [%4];"
        : "=r"(r[0]), "=r"(r[1]), "=r"(r[2]), "=r"(r[3]) : "r"(addr));
}
__device__ __forceinline__ void cp16(uint32_t sm, const void* g) {
    asm volatile("cp.async.cg.shared.global [%0], [%1], 16;" :: "r"(sm), "l"(g));
}
#define CP_COMMIT() asm volatile("cp.async.commit_group;" ::: "memory")
#define CP_WAIT(n)  asm volatile("cp.async.wait_group %0;" :: "n"(n) : "memory")

__device__ __forceinline__ void split1(float x, __nv_bfloat16& h, __nv_bfloat16& l) {
    h = __float2bfloat16(x);
    l = __float2bfloat16(x - __bfloat162float(h));
}
__device__ __forceinline__ uint32_t pack2(__nv_bfloat16 a, __nv_bfloat16 b) {
    return (uint32_t)__bfloat16_as_ushort(a) | ((uint32_t)__bfloat16_as_ushort(b) << 16);
}
__device__ __forceinline__ void split4(float4 v, uint2& hw, uint2& lw) {
    __nv_bfloat16 h0, h1, h2, h3, l0, l1, l2, l3;
    split1(v.x, h0, l0); split1(v.y, h1, l1);
    split1(v.z, h2, l2); split1(v.w, h3, l3);
    hw.x = pack2(h0, h1); hw.y = pack2(h2, h3);
    lw.x = pack2(l0, l1); lw.y = pack2(l2, l3);
}

// ===========================================================================
// single merged fp32 -> bf16 hi/lo converter for all 7 tensors
// grid = (1024, 7): y in {0,1,2} -> q/k/v (8 chunks of 1M elems each),
//                   y in {3..6} -> Wq/Wk/Wv/Wo (1 chunk of 1M elems)
// ===========================================================================
__global__ void conv_all(const float* __restrict__ q, const float* __restrict__ k,
                         const float* __restrict__ v,
                         const float* __restrict__ w0, const float* __restrict__ w1,
                         const float* __restrict__ w2, const float* __restrict__ w3,
                         __nv_bfloat16* __restrict__ qh, __nv_bfloat16* __restrict__ ql,
                         __nv_bfloat16* __restrict__ kh, __nv_bfloat16* __restrict__ kl,
                         __nv_bfloat16* __restrict__ vh, __nv_bfloat16* __restrict__ vl,
                         __nv_bfloat16* __restrict__ wh0, __nv_bfloat16* __restrict__ wl0,
                         __nv_bfloat16* __restrict__ wh1, __nv_bfloat16* __restrict__ wl1,
                         __nv_bfloat16* __restrict__ wh2, __nv_bfloat16* __restrict__ wl2,
                         __nv_bfloat16* __restrict__ wh3, __nv_bfloat16* __restrict__ wl3)
{
    const int y = blockIdx.y;
    const float* x;
    __nv_bfloat16 *h, *l;
    int nch;
    switch (y) {
        case 0: x = q;  h = qh;  l = ql;  nch = 8; break;
        case 1: x = k;  h = kh;  l = kl;  nch = 8; break;
        case 2: x = v;  h = vh;  l = vl;  nch = 8; break;
        case 3: x = w0; h = wh0; l = wl0; nch = 1; break;
        case 4: x = w1; h = wh1; l = wl1; nch = 1; break;
        case 5: x = w2; h = wh2; l = wl2; nch = 1; break;
        default: x = w3; h = wh3; l = wl3; nch = 1; break;
    }
    for (int c = 0; c < nch; c++) {
        int i = (((c * 1024 + blockIdx.x) * 256) + threadIdx.x) * 4;
        float4 vv = *(const float4*)(x + i);
        uint2 hw, lw;
        split4(vv, hw, lw);
        *(uint2*)(h + i) = hw;
        *(uint2*)(l + i) = lw;
    }
}

// ===========================================================================
// Merged mask dtype sniff + normalization: each block independently re-scans
// the full mask (8 KB) to classify dtype, then normalizes its own slice.
//   - all bytes at idx%4!=0 zero -> int32 (0/1 LE)
//   - else all at idx%4==0 zero  -> float32 (1.0f = 00 00 80 3F)
//   - else                       -> uint8 bool
// ===========================================================================
__global__ void mask_all(const void* __restrict__ m)
{
    __shared__ int nz_off, nz_al;
    if (threadIdx.x == 0) { nz_off = 0; nz_al = 0; }
    __syncthreads();
    const unsigned char* mb = (const unsigned char*)m;
    int loc_off = 0, loc_al = 0;
    for (int i = threadIdx.x; i < NMASK; i += blockDim.x) {
        unsigned char v = mb[i];
        if (v) { if (i & 3) loc_off = 1; else loc_al = 1; }
    }
    if (loc_off) atomicOr(&nz_off, 1);
    if (loc_al)  atomicOr(&nz_al, 1);
    __syncthreads();
    const int kind = (!nz_off) ? 1 : (!nz_al) ? 2 : 0;
    int i = blockIdx.x * blockDim.x + threadIdx.x;
    unsigned char r;
    if (kind == 1)      r = (((const int*)m)[i]   != 0);
    else if (kind == 2) r = (((const float*)m)[i] != 0.f);
    else                r = (mb[i] != 0);
    g_mask[i] = r;
}

// ===========================================================================
// HMMA GEMM NT core (R13/R14-proven body): C = A*B^T, bf16 hi/lo x3 chains,
// cp.async 2-stage (issue -> commit -> wait(1) -> sync -> compute -> sync).
// ===========================================================================
#define GBM 128
#define GBN 128
#define GBK 32
#define GSTR 40
#define ARR_SZ (128 * GSTR * 2)
#define STAGE_SZ (4 * ARR_SZ)
#define GEMM_SMEM (2 * STAGE_SZ)
#define O_AH 0
#define O_AL ARR_SZ
#define O_BH (2 * ARR_SZ)
#define O_BL (3 * ARR_SZ)

extern __shared__ char sm_raw[];

template <int OUTMODE>
__device__ __forceinline__ void gemm_core(
    const __nv_bfloat16* __restrict__ Agh, const __nv_bfloat16* __restrict__ Agl,
    const __nv_bfloat16* __restrict__ Bgh, const __nv_bfloat16* __restrict__ Bgl,
    float* __restrict__ Cf,
    __nv_bfloat16* __restrict__ Ch, __nv_bfloat16* __restrict__ Cl)
{
    uint32_t sb = smem_u32(sm_raw);
    const int tid = threadIdx.x;
    const int wid = tid >> 5;
    const int lane = tid & 31;
    const int wm = (wid & 1) * 64;
    const int wn = (wid >> 1) * 32;
    const size_t rowA0 = (size_t)blockIdx.y * GBM;
    const size_t rowB0 = (size_t)blockIdx.x * GBN;

    const int carr = tid >> 6;
    const int crow0 = (tid & 63) >> 1;
    const int cseg = (tid & 1) << 1;
    const __nv_bfloat16* gbase[4] = {
        Agh + rowA0 * EMB, Agl + rowA0 * EMB,
        Bgh + rowB0 * EMB, Bgl + rowB0 * EMB };
    const __nv_bfloat16* mygb = gbase[carr];
    const uint32_t myarr = sb + carr * ARR_SZ;

    float acc[4][4][4];
#pragma unroll
    for (int mt = 0; mt < 4; mt++)
#pragma unroll
        for (int nt = 0; nt < 4; nt++)
#pragma unroll
            for (int e = 0; e < 4; e++) acc[mt][nt][e] = 0.f;

    const int NCH = EMB / GBK;   // 32

#pragma unroll
    for (int rr = 0; rr < 4; rr++) {
        int row = crow0 + rr * 32;
        uint32_t smaddr = myarr + row * (GSTR * 2) + cseg * 16;
        const void* g = mygb + (size_t)row * EMB + cseg * 8;
        cp16(smaddr, g);
        cp16(smaddr + 16, (const char*)g + 16);
    }
    CP_COMMIT();

    for (int c = 0; c < NCH; c++) {
        if (c + 1 < NCH) {
            const int kt = (c + 1) * GBK;
            const uint32_t stb = myarr + ((c + 1) & 1) * STAGE_SZ;
#pragma unroll
            for (int rr = 0; rr < 4; rr++) {
                int row = crow0 + rr * 32;
                uint32_t smaddr = stb + row * (GSTR * 2) + cseg * 16;
                const void* g = mygb + (size_t)row * EMB + kt + cseg * 8;
                cp16(smaddr, g);
                cp16(smaddr + 16, (const char*)g + 16);
            }
            CP_COMMIT();
            CP_WAIT(1);
        } else {
            CP_WAIT(0);
        }
        __syncthreads();

        const uint32_t base = sb + (uint32_t)(c & 1) * STAGE_SZ;
        const uint32_t lrow = lane & 15;
        const uint32_t lcol = (lane >> 4) << 3;
#pragma unroll
        for (int kk = 0; kk < GBK; kk += 16) {
            uint32_t af[4][4];
#pragma unroll
            for (int mt = 0; mt < 4; mt++) {
                uint32_t addr = base + O_AH +
                    (uint32_t)(((wm + mt * 16 + lrow) * GSTR + kk + lcol) * 2);
                ldsm_x4(af[mt], addr);
            }
            uint32_t b0h[4], b1h[4], b0l[4], b1l[4];
#pragma unroll
            for (int g = 0; g < 2; g++) {
                uint32_t roff = (uint32_t)(((wn + g * 16 + lrow) * GSTR + kk + lcol) * 2);
                uint32_t r4[4];
                ldsm_x4(r4, base + O_BH + roff);
                b0h[2 * g] = r4[0]; b0h[2 * g + 1] = r4[1];
                b1h[2 * g] = r4[2]; b1h[2 * g + 1] = r4[3];
                ldsm_x4(r4, base + O_BL + roff);
                b0l[2 * g] = r4[0]; b0l[2 * g + 1] = r4[1];
                b1l[2 * g] = r4[2]; b1l[2 * g + 1] = r4[3];
            }
#pragma unroll
            for (int mt = 0; mt < 4; mt++)
#pragma unroll
                for (int nt = 0; nt < 4; nt++) {
                    mma16816(acc[mt][nt], af[mt], b0h[nt], b1h[nt]);
                    mma16816(acc[mt][nt], af[mt], b0l[nt], b1l[nt]);
                }
#pragma unroll
            for (int mt = 0; mt < 4; mt++) {
                uint32_t addr = base + O_AL +
                    (uint32_t)(((wm + mt * 16 + lrow) * GSTR + kk + lcol) * 2);
                ldsm_x4(af[mt], addr);
            }
#pragma unroll
            for (int mt = 0; mt < 4; mt++)
#pragma unroll
                for (int nt = 0; nt < 4; nt++)
                    mma16816(acc[mt][nt], af[mt], b0h[nt], b1h[nt]);
        }
        __syncthreads();
    }

#pragma unroll
    for (int mt = 0; mt < 4; mt++) {
        size_t r0 = rowA0 + wm + mt * 16 + (lane >> 2);
        size_t r1 = r0 + 8;
#pragma unroll
        for (int nt = 0; nt < 4; nt++) {
            size_t cc = rowB0 + wn + nt * 8 + (lane & 3) * 2;
            if (OUTMODE == 0) {
                *(float2*)(Cf + r0 * EMB + cc) = make_float2(acc[mt][nt][0], acc[mt][nt][1]);
                *(float2*)(Cf + r1 * EMB + cc) = make_float2(acc[mt][nt][2], acc[mt][nt][3]);
            } else {
                __nv_bfloat16 h0, l0, h1, l1;
                split1(acc[mt][nt][0], h0, l0);
                split1(acc[mt][nt][1], h1, l1);
                *(uint32_t*)(Ch + r0 * EMB + cc) = pack2(h0, h1);
                *(uint32_t*)(Cl + r0 * EMB + cc) = pack2(l0, l1);
                split1(acc[mt][nt][2], h0, l0);
                split1(acc[mt][nt][3], h1, l1);
                *(uint32_t*)(Ch + r1 * EMB + cc) = pack2(h0, h1);
                *(uint32_t*)(Cl + r1 * EMB + cc) = pack2(l0, l1);
            }
        }
    }
}

// Merged Q/K/V projection launch: blockIdx.z selects the problem.
__global__ __launch_bounds__(256, 2) void gemm_qkv(
    const __nv_bfloat16* qh, const __nv_bfloat16* ql,
    const __nv_bfloat16* kh, const __nv_bfloat16* kl,
    const __nv_bfloat16* vh, const __nv_bfloat16* vl,
    const __nv_bfloat16* wqh, const __nv_bfloat16* wql,
    const __nv_bfloat16* wkh, const __nv_bfloat16* wkl,
    const __nv_bfloat16* wvh, const __nv_bfloat16* wvl,
    __nv_bfloat16* pqh, __nv_bfloat16* pql,
    __nv_bfloat16* pkh, __nv_bfloat16* pkl,
    __nv_bfloat16* pvh, __nv_bfloat16* pvl)
{
    const int z = blockIdx.z;
    const __nv_bfloat16* Agh = (z == 0) ? qh : (z == 1) ? kh : vh;
    const __nv_bfloat16* Agl = (z == 0) ? ql : (z == 1) ? kl : vl;
    const __nv_bfloat16* Bgh = (z == 0) ? wqh : (z == 1) ? wkh : wvh;
    const __nv_bfloat16* Bgl = (z == 0) ? wql : (z == 1) ? wkl : wvl;
    __nv_bfloat16* Ch = (z == 0) ? pqh : (z == 1) ? pkh : pvh;
    __nv_bfloat16* Cl = (z == 0) ? pql : (z == 1) ? pkl : pvl;
    gemm_core<1>(Agh, Agl, Bgh, Bgl, nullptr, Ch, Cl);
}

__global__ __launch_bounds__(256, 2) void gemm_out(
    const __nv_bfloat16* Agh, const __nv_bfloat16* Agl,
    const __nv_bfloat16* Bgh, const __nv_bfloat16* Bgl,
    float* Cf)
{
    gemm_core<0>(Agh, Agl, Bgh, Bgl, Cf, nullptr, nullptr);
}

// ===========================================================================
// FA2-style flash attention (R13-proven, race-free): 128 q/CTA,
// warp = 16q x 64k, register softmax, P register-resident,
// cp.async double-buffered K/V with trailing barrier.
// ===========================================================================
#define AQ 128
#define AK 64
#define ASTR 72
#define AROWB (ASTR * 2)       // 144 B per smem row
#define KVROWS (AK * AROWB)    // 9216 B per K/V array per stage

struct AttnSmem {
    __nv_bfloat16 Qh[AQ][ASTR], Ql[AQ][ASTR];
    __nv_bfloat16 Kh[2][AK][ASTR], Kl[2][AK][ASTR];
    __nv_bfloat16 Vh[2][AK][ASTR], Vl[2][AK][ASTR];
    unsigned char msk[2][64];
};
#define ATTN_SMEM ((int)sizeof(AttnSmem))

__global__ __launch_bounds__(256) void attn_mma(
    const __nv_bfloat16* __restrict__ Qhg, const __nv_bfloat16* __restrict__ Qlg,
    const __nv_bfloat16* __restrict__ Khg, const __nv_bfloat16* __restrict__ Klg,
    const __nv_bfloat16* __restrict__ Vhg, const __nv_bfloat16* __restrict__ Vlg,
    const unsigned char* __restrict__ mask,
    __nv_bfloat16* __restrict__ Ohg, __nv_bfloat16* __restrict__ Olg)
{
    AttnSmem& s = *reinterpret_cast<AttnSmem*>(sm_raw);
    const int b  = blockIdx.z;
    const int h  = blockIdx.y;
    const int qt = blockIdx.x;
    const int tid = threadIdx.x;
    const int wid = tid >> 5;
    const int lane = tid & 31;
    const size_t headoff = (size_t)h * HDIM;

    const uint32_t sqh = smem_u32(&s.Qh[0][0]);
    const uint32_t sql = smem_u32(&s.Ql[0][0]);
    const uint32_t skh = smem_u32(&s.Kh[0][0][0]);
    const uint32_t skl = smem_u32(&s.Kl[0][0][0]);
    const uint32_t svh = smem_u32(&s.Vh[0][0][0]);
    const uint32_t svl = smem_u32(&s.Vl[0][0][0]);
    const uint32_t smk = smem_u32(&s.msk[0][0]);

    // --- Q tile load: 128 x 64 hi/lo, 16B vector loads ---
#pragma unroll
    for (int t = 0; t < 4; t++) {
        int i = tid + t * 256;            // 0..1023
        int r = i >> 3, seg = i & 7;      // row, 16B segment
        size_t gi = ((size_t)(qt * AQ + r) * BATCH + b) * EMB + headoff + seg * 8;
        *(uint4*)((char*)&s.Qh[r][0] + seg * 16) = *(const uint4*)(Qhg + gi);
        *(uint4*)((char*)&s.Ql[r][0] + seg * 16) = *(const uint4*)(Qlg + gi);
    }

    // --- cp.async assignment: tid>>6 -> array, tid&63 -> row (8 x 16B) ---
    const int ca = tid >> 6;
    const int crow = tid & 63;
    const __nv_bfloat16* casrc = (ca == 0) ? Khg : (ca == 1) ? Klg
                                : (ca == 2) ? Vhg : Vlg;
    const uint32_t cadst = (ca == 0) ? skh : (ca == 1) ? skl
                          : (ca == 2) ? svh : svl;

    // prefetch k-tile 0 into stage 0
    {
        size_t gi = ((size_t)crow * BATCH + b) * EMB + headoff;
        const char* g = (const char*)(casrc + gi);
        uint32_t d = cadst + crow * AROWB;
#pragma unroll
        for (int seg = 0; seg < 8; seg++) cp16(d + seg * 16, g + seg * 16);
        if (tid < 4) cp16(smk + tid * 16, mask + (size_t)b * T_K + tid * 16);
    }
    CP_COMMIT();

    float m0 = -INFINITY, m1 = -INFINITY, l0 = 0.f, l1 = 0.f;
    float o[8][4];
#pragma unroll
    for (int nt = 0; nt < 8; nt++)
#pragma unroll
        for (int e = 0; e < 4; e++) o[nt][e] = 0.f;

    const uint32_t lrow = lane & 15;
    const uint32_t lcol = (lane >> 4) << 3;
    const int NT = T_K / AK;     // 32

    for (int kt = 0; kt < NT; kt++) {
        if (kt + 1 < NT) {
            int st2 = (kt + 1) & 1;
            size_t gi = ((size_t)((kt + 1) * AK + crow) * BATCH + b) * EMB + headoff;
            const char* g = (const char*)(casrc + gi);
            uint32_t d = cadst + st2 * KVROWS + crow * AROWB;
#pragma unroll
            for (int seg = 0; seg < 8; seg++) cp16(d + seg * 16, g + seg * 16);
            if (tid < 4)
                cp16(smk + st2 * 64 + tid * 16,
                     mask + (size_t)b * T_K + (kt + 1) * AK + tid * 16);
            CP_COMMIT();
            CP_WAIT(1);
        } else {
            CP_WAIT(0);
        }
        __syncthreads();

        const int st = kt & 1;
        const uint32_t kbh = skh + st * KVROWS;
        const uint32_t kbl = skl + st * KVROWS;
        const uint32_t vbh = svh + st * KVROWS;
        const uint32_t vbl = svl + st * KVROWS;
        const unsigned char* mrow = &s.msk[st][0];

        // ---- S = Q K^T (warp: 16q x 64k), 3 chains ----
        float sc[8][4];
#pragma unroll
        for (int nt = 0; nt < 8; nt++)
#pragma unroll
            for (int e = 0; e < 4; e++) sc[nt][e] = 0.f;

#pragma unroll
        for (int kk = 0; kk < 4; kk++) {
            uint32_t aoff = (uint32_t)(((wid * 16 + lrow) * ASTR + kk * 16 + lcol) * 2);
            uint32_t ah[4], al[4];
            ldsm_x4(ah, sqh + aoff);
            ldsm_x4(al, sql + aoff);
            uint32_t b0h[8], b1h[8], b0l[8], b1l[8];
#pragma unroll
            for (int g = 0; g < 4; g++) {
                uint32_t roff = (uint32_t)(((g * 16 + lrow) * ASTR + kk * 16 + lcol) * 2);
                uint32_t r4[4];
                ldsm_x4(r4, kbh + roff);
                b0h[2*g] = r4[0]; b0h[2*g+1] = r4[1];
                b1h[2*g] = r4[2]; b1h[2*g+1] = r4[3];
                ldsm_x4(r4, kbl + roff);
                b0l[2*g] = r4[0]; b0l[2*g+1] = r4[1];
                b1l[2*g] = r4[2]; b1l[2*g+1] = r4[3];
            }
#pragma unroll
            for (int nt = 0; nt < 8; nt++) {
                mma16816(sc[nt], ah, b0h[nt], b1h[nt]);
                mma16816(sc[nt], ah, b0l[nt], b1l[nt]);
                mma16816(sc[nt], al, b0h[nt], b1h[nt]);
            }
        }

        // ---- register softmax ----
        float tm0 = -INFINITY, tm1 = -INFINITY;
#pragma unroll
        for (int nt = 0; nt < 8; nt++) {
            int k0 = nt * 8 + (lane & 3) * 2;
            bool mk0 = mrow[k0] != 0, mk1 = mrow[k0 + 1] != 0;
            sc[nt][0] = mk0 ? NEGINF : sc[nt][0] * 0.125f;
            sc[nt][1] = mk1 ? NEGINF : sc[nt][1] * 0.125f;
            sc[nt][2] = mk0 ? NEGINF : sc[nt][2] * 0.125f;
            sc[nt][3] = mk1 ? NEGINF : sc[nt][3] * 0.125f;
            tm0 = fmaxf(tm0, fmaxf(sc[nt][0], sc[nt][1]));
            tm1 = fmaxf(tm1, fmaxf(sc[nt][2], sc[nt][3]));
        }
        tm0 = fmaxf(tm0, __shfl_xor_sync(0xffffffffu, tm0, 1));
        tm0 = fmaxf(tm0, __shfl_xor_sync(0xffffffffu, tm0, 2));
        tm1 = fmaxf(tm1, __shfl_xor_sync(0xffffffffu, tm1, 1));
        tm1 = fmaxf(tm1, __shfl_xor_sync(0xffffffffu, tm1, 2));

        float mn0 = fmaxf(m0, tm0), mn1 = fmaxf(m1, tm1);
        float al0 = __expf(m0 - mn0), al1 = __expf(m1 - mn1);
        m0 = mn0; m1 = mn1;

        float ts0 = 0.f, ts1 = 0.f;
        uint32_t pfh[4][4], pfl[4][4];
#pragma unroll
        for (int nt = 0; nt < 8; nt++) {
            float p0 = __expf(sc[nt][0] - mn0);
            float p1 = __expf(sc[nt][1] - mn0);
            float p2 = __expf(sc[nt][2] - mn1);
            float p3 = __expf(sc[nt][3] - mn1);
            ts0 += p0 + p1;
            ts1 += p2 + p3;
            __nv_bfloat16 h0, lo0, h1, lo1;
            int t = nt >> 1, half = (nt & 1) * 2;
            split1(p0, h0, lo0); split1(p1, h1, lo1);
            pfh[t][half + 0] = pack2(h0, h1);
            pfl[t][half + 0] = pack2(lo0, lo1);
            split1(p2, h0, lo0); split1(p3, h1, lo1);
            pfh[t][half + 1] = pack2(h0, h1);
            pfl[t][half + 1] = pack2(lo0, lo1);
        }
        ts0 += __shfl_xor_sync(0xffffffffu, ts0, 1);
        ts0 += __shfl_xor_sync(0xffffffffu, ts0, 2);
        ts1 += __shfl_xor_sync(0xffffffffu, ts1, 1);
        ts1 += __shfl_xor_sync(0xffffffffu, ts1, 2);
        l0 = l0 * al0 + ts0;
        l1 = l1 * al1 + ts1;

#pragma unroll
        for (int nt = 0; nt < 8; nt++) {
            o[nt][0] *= al0; o[nt][1] *= al0;
            o[nt][2] *= al1; o[nt][3] *= al1;
        }

        // ---- O += P V (warp: 16q x 64d), 3 chains ----
#pragma unroll
        for (int t = 0; t < 4; t++) {
            uint32_t b0h[8], b1h[8], b0l[8], b1l[8];
#pragma unroll
            for (int g = 0; g < 4; g++) {
                uint32_t vrow = (uint32_t)(t * 16 + (lane & 7) + ((lane >> 3) & 1) * 8);
                uint32_t vcol = (uint32_t)(g * 16 + ((lane >> 4) << 3));
                uint32_t roff = (vrow * ASTR + vcol) * 2;
                uint32_t r4[4];
                ldsm_x4_t(r4, vbh + roff);
                b0h[2*g] = r4[0]; b1h[2*g] = r4[1];
                b0h[2*g+1] = r4[2]; b1h[2*g+1] = r4[3];
                ldsm_x4_t(r4, vbl + roff);
                b0l[2*g] = r4[0]; b1l[2*g] = r4[1];
                b0l[2*g+1] = r4[2]; b1l[2*g+1] = r4[3];
            }
#pragma unroll
            for (int nt = 0; nt < 8; nt++) {
                mma16816(o[nt], pfh[t], b0h[nt], b1h[nt]);
                mma16816(o[nt], pfh[t], b0l[nt], b1l[nt]);
                mma16816(o[nt], pfl[t], b0h[nt], b1h[nt]);
            }
        }

        // RACE FIX: all warps must finish reading stage `st` before the next
        // iteration issues cp.async writes into it.
        __syncthreads();
    }

    // ---- finalize: /l, write bf16 hi/lo AO at (t, b, e) ----
    float inv0 = 1.f / l0;
    float inv1 = 1.f / l1;
    const int r0 = wid * 16 + (lane >> 2);
    const int r1 = r0 + 8;
    size_t tg0 = (size_t)(qt * AQ + r0) * BATCH + b;
    size_t tg1 = (size_t)(qt * AQ + r1) * BATCH + b;
#pragma unroll
    for (int nt = 0; nt < 8; nt++) {
        size_t d0 = nt * 8 + (lane & 3) * 2;
        __nv_bfloat16 h0, lo0, h1, lo1;
        split1(o[nt][0] * inv0, h0, lo0);
        split1(o[nt][1] * inv0, h1, lo1);
        *(uint32_t*)(Ohg + tg0 * EMB + headoff + d0) = pack2(h0, h1);
        *(uint32_t*)(Olg + tg0 * EMB + headoff + d0) = pack2(lo0, lo1);
        split1(o[nt][2] * inv1, h0, lo0);
        split1(o[nt][3] * inv1, h1, lo1);
        *(uint32_t*)(Ohg + tg1 * EMB + headoff + d0) = pack2(h0, h1);
        *(uint32_t*)(Olg + tg1 * EMB + headoff + d0) = pack2(lo0, lo1);
    }
}

// ===========================================================================
// Launch
// ===========================================================================
extern "C" void kernel_launch(void* const* d_in, const int* in_sizes, int n_in,
                              void* d_out, int out_size)
{
    const float* q  = (const float*)d_in[0];
    const float* k  = (const float*)d_in[1];
    const float* v  = (const float*)d_in[2];
    const void*  maskraw = d_in[3];
    const float* Wq = (const float*)d_in[4];
    const float* Wk = (const float*)d_in[5];
    const float* Wv = (const float*)d_in[6];
    const float* Wo = (const float*)d_in[7];
    float* out = (float*)d_out;

    __nv_bfloat16 *qh, *ql, *kh, *kl, *vh, *vl;
    __nv_bfloat16 *wqh, *wql, *wkh, *wkl, *wvh, *wvl, *woh, *wol;
    __nv_bfloat16 *pqh, *pql, *pkh, *pkl, *pvh, *pvl, *aoh, *aol;
    unsigned char* gmask;
    cudaGetSymbolAddress((void**)&qh, c_qh);  cudaGetSymbolAddress((void**)&ql, c_ql);
    cudaGetSymbolAddress((void**)&kh, c_kh);  cudaGetSymbolAddress((void**)&kl, c_kl);
    cudaGetSymbolAddress((void**)&vh, c_vh);  cudaGetSymbolAddress((void**)&vl, c_vl);
    cudaGetSymbolAddress((void**)&wqh, c_wqh); cudaGetSymbolAddress((void**)&wql, c_wql);
    cudaGetSymbolAddress((void**)&wkh, c_wkh); cudaGetSymbolAddress((void**)&wkl, c_wkl);
    cudaGetSymbolAddress((void**)&wvh, c_wvh); cudaGetSymbolAddress((void**)&wvl, c_wvl);
    cudaGetSymbolAddress((void**)&woh, c_woh); cudaGetSymbolAddress((void**)&wol, c_wol);
    cudaGetSymbolAddress((void**)&pqh, p_qh);  cudaGetSymbolAddress((void**)&pql, p_ql);
    cudaGetSymbolAddress((void**)&pkh, p_kh);  cudaGetSymbolAddress((void**)&pkl, p_kl);
    cudaGetSymbolAddress((void**)&pvh, p_vh);  cudaGetSymbolAddress((void**)&pvl, p_vl);
    cudaGetSymbolAddress((void**)&aoh, ao_h);  cudaGetSymbolAddress((void**)&aol, ao_l);
    cudaGetSymbolAddress((void**)&gmask, g_mask);

    cudaFuncSetAttribute(attn_mma, cudaFuncAttributeMaxDynamicSharedMemorySize,
                         ATTN_SMEM);
    cudaFuncSetAttribute(gemm_qkv, cudaFuncAttributeMaxDynamicSharedMemorySize,
                         GEMM_SMEM);
    cudaFuncSetAttribute(gemm_out, cudaFuncAttributeMaxDynamicSharedMemorySize,
                         GEMM_SMEM);

    mask_all<<<NMASK / 256, 256>>>(maskraw);

    conv_all<<<dim3(1024, 7), 256>>>(q, k, v, Wq, Wk, Wv, Wo,
                                     qh, ql, kh, kl, vh, vl,
                                     wqh, wql, wkh, wkl,
                                     wvh, wvl, woh, wol);

    dim3 ggrid3(EMB / GBN, MROWS / GBM, 3);   // (8, 64, 3)
    gemm_qkv<<<ggrid3, 256, GEMM_SMEM>>>(qh, ql, kh, kl, vh, vl,
                                         wqh, wql, wkh, wkl, wvh, wvl,
                                         pqh, pql, pkh, pkl, pvh, pvl);

    dim3 agrid(T_Q / AQ, NHEADS, BATCH);  // (16, 16, 4)
    attn_mma<<<agrid, 256, ATTN_SMEM>>>(pqh, pql, pkh, pkl, pvh, pvl, gmask,
                                        aoh, aol);

    dim3 ggrid(EMB / GBN, MROWS / GBM);   // (8, 64)
    gemm_out<<<ggrid, 256, GEMM_SMEM>>>(aoh, aol, woh, wol, out);
}